// round 11
// baseline (speedup 1.0000x reference)
#include <cuda_runtime.h>
#include <cuda_fp16.h>
#include <cstdint>

// Problem constants (fixed shapes from reference setup_inputs)
#define BB 4
#define NN 3137          // 1 + 16*196
#define DIM 1024
#define HH 16
#define HD 64
#define FF 16
#define NS 196
#define BH (BB*HH)       // 64
#define M_TOT (BB*NN)    // 12548
#define QSCALE 0.125f    // 64^-0.5
#define NSM2 296         // 2 CTAs x 148 SMs (persistent grid)

// Scratch in device globals (no allocations allowed)
__device__ __half g_xh[(size_t)M_TOT * DIM];         // fp16 copy of x
__device__ __half g_wqkvh[(size_t)3 * DIM * DIM];    // fp16 qkv_w
__device__ __half g_wprojh[(size_t)DIM * DIM];       // fp16 proj_w
__device__ __half g_qh[(size_t)BH * NN * HD];        // head-major, pre-scaled
__device__ __half g_kh[(size_t)BH * NN * HD];
__device__ __half g_vh[(size_t)BH * NN * HD];
__device__ __half g_attnh[(size_t)BB * NN * DIM];    // (B, N, H*HD) attention out

// ---------------- helpers ----------------
__device__ __forceinline__ void mma_f16(float4& c, const uint32_t a[4], const uint32_t b[2]) {
    asm volatile(
        "mma.sync.aligned.m16n8k16.row.col.f32.f16.f16.f32 "
        "{%0,%1,%2,%3}, {%4,%5,%6,%7}, {%8,%9}, {%0,%1,%2,%3};"
        : "+f"(c.x), "+f"(c.y), "+f"(c.z), "+f"(c.w)
        : "r"(a[0]), "r"(a[1]), "r"(a[2]), "r"(a[3]), "r"(b[0]), "r"(b[1]));
}

__device__ __forceinline__ void ldmatrix_x4(uint32_t* r, uint32_t addr) {
    asm volatile("ldmatrix.sync.aligned.m8n8.x4.shared.b16 {%0,%1,%2,%3}, [%4];"
                 : "=r"(r[0]), "=r"(r[1]), "=r"(r[2]), "=r"(r[3]) : "r"(addr));
}
__device__ __forceinline__ void ldmatrix_x2(uint32_t* r, uint32_t addr) {
    asm volatile("ldmatrix.sync.aligned.m8n8.x2.shared.b16 {%0,%1}, [%2];"
                 : "=r"(r[0]), "=r"(r[1]) : "r"(addr));
}

__device__ __forceinline__ void cp_async16(uint32_t dst_smem, const void* src, int src_bytes) {
    asm volatile("cp.async.cg.shared.global [%0], [%1], 16, %2;"
                 :: "r"(dst_smem), "l"(src), "r"(src_bytes));
}
__device__ __forceinline__ void cp_commit() {
    asm volatile("cp.async.commit_group;");
}
template <int N>
__device__ __forceinline__ void cp_wait() {
    asm volatile("cp.async.wait_group %0;" :: "n"(N));
}

// ---------------------------------------------------------------------------
// fp32 -> fp16 conversion, all three operand arrays in one launch.
// ---------------------------------------------------------------------------
#define N8X (M_TOT * DIM / 8)
#define N8Q (3 * DIM * DIM / 8)
#define N8P (DIM * DIM / 8)

__global__ void __launch_bounds__(256)
cvt_all_kernel(const float* __restrict__ x, const float* __restrict__ wq,
               const float* __restrict__ wp)
{
    const int i = blockIdx.x * blockDim.x + threadIdx.x;
    const float* src;
    __half* dst;
    int off;
    if (i < N8X) {
        __half* p; p = g_xh; dst = p; src = x; off = i;
    } else if (i < N8X + N8Q) {
        dst = g_wqkvh; src = wq; off = i - N8X;
    } else if (i < N8X + N8Q + N8P) {
        dst = g_wprojh; src = wp; off = i - N8X - N8Q;
    } else {
        return;
    }
    const float4 a = ((const float4*)src)[off * 2];
    const float4 b = ((const float4*)src)[off * 2 + 1];
    __half2 h[4];
    h[0] = __floats2half2_rn(a.x, a.y);
    h[1] = __floats2half2_rn(a.z, a.w);
    h[2] = __floats2half2_rn(b.x, b.y);
    h[3] = __floats2half2_rn(b.z, b.w);
    ((uint4*)dst)[off] = *(uint4*)h;
}

// ---------------------------------------------------------------------------
// Persistent fp16 tensor-core GEMM, 4-stage cp.async, ldmatrix loads.
// Grid = NSM2 fixed CTAs looping over 128x128 tile jobs.
// C[m,n] = sum_k A[m,k] * W[n,k] + bias[n]
// MODE 0: A = g_xh, W = g_wqkvh; epilogue scatters fp16 into g_qh/g_kh/g_vh
// MODE 1: A = g_attnh, W = g_wprojh; epilogue writes fp32 Cout + bias
// Between jobs no extra barrier: the prologue's stages 0..2 are fully
// consumed by all warps before the final k-iteration's barrier.
// ---------------------------------------------------------------------------
#define ASTR 40
#define TILEH (128 * ASTR)            // halves per A or B tile
#define STG_BYTES (2 * TILEH * 2)     // A+B per stage (20480)
#define GSMEM (4 * STG_BYTES)         // 81920 B

template <int MODE>
__global__ void __launch_bounds__(256, 2)
gemm_fp16_kernel(const float* __restrict__ bias, float* __restrict__ Cout,
                 int M, int Nn, int K, int njobs, int ntiles_n)
{
    extern __shared__ __align__(16) uint8_t dsm[];
    const uint32_t sbase = (uint32_t)__cvta_generic_to_shared(dsm);

    const __half* Ah = (MODE == 1) ? g_attnh : g_xh;
    const __half* Bh = (MODE == 1) ? g_wprojh : g_wqkvh;

    const int tid = threadIdx.x;
    const int warp = tid >> 5, lane = tid & 31;
    const int grp = lane >> 2, qid = lane & 3;
    const int wm = warp & 3;       // m offset 32*wm
    const int wn = warp >> 2;      // n offset 64*wn

    // ldmatrix lane-address components
    const int lm_row16 = lane & 15;
    const int lm_ka    = (lane >> 4) << 3;
    const int lm_rowb  = ((lane >> 4) << 3) + (lane & 7);
    const int lm_kb    = ((lane >> 3) & 1) << 3;

    const int T = K / 32;

    for (int j = blockIdx.x; j < njobs; j += gridDim.x) {
        const int n0 = (j % ntiles_n) * 128;
        const int m0 = (j / ntiles_n) * 128;

        float4 acc[2][8];
#pragma unroll
        for (int i = 0; i < 2; i++)
#pragma unroll
            for (int jj = 0; jj < 8; jj++) acc[i][jj] = make_float4(0.f, 0.f, 0.f, 0.f);

        auto load_tile = [&](int t, int stg) {
            const int k0 = t * 32;
            const uint32_t ab = sbase + stg * STG_BYTES;
            const uint32_t bb = ab + TILEH * 2;
#pragma unroll
            for (int i = 0; i < 2; i++) {
                const int c = tid + i * 256;        // 0..511
                const int row = c >> 2, ch = c & 3;
                const int gm = m0 + row;
                const __half* asrc = &Ah[(size_t)((gm < M) ? gm : (M - 1)) * K + k0 + ch * 8];
                cp_async16(ab + (uint32_t)(row * ASTR + ch * 8) * 2, asrc, (gm < M) ? 16 : 0);
                cp_async16(bb + (uint32_t)(row * ASTR + ch * 8) * 2,
                           &Bh[(size_t)(n0 + row) * K + k0 + ch * 8], 16);
            }
            cp_commit();
        };

        load_tile(0, 0);
        load_tile(1, 1);
        load_tile(2, 2);

        for (int t = 0; t < T; t++) {
            if (t + 2 < T)      cp_wait<2>();
            else if (t + 1 < T) cp_wait<1>();
            else                cp_wait<0>();
            __syncthreads();                 // tile t visible; stage (t+3)%4 consumed
            if (t + 3 < T) load_tile(t + 3, (t + 3) & 3);

            const uint32_t ab = sbase + (t & 3) * STG_BYTES;
            const uint32_t bb = ab + TILEH * 2;
#pragma unroll
            for (int s = 0; s < 2; s++) {
                uint32_t a[2][4];
#pragma unroll
                for (int mi = 0; mi < 2; mi++)
                    ldmatrix_x4(a[mi], ab + (uint32_t)((wm * 32 + mi * 16 + lm_row16) * ASTR
                                                       + s * 16 + lm_ka) * 2);
                uint32_t b[8][2];
#pragma unroll
                for (int p = 0; p < 4; p++) {
                    uint32_t t4[4];
                    ldmatrix_x4(t4, bb + (uint32_t)((wn * 64 + p * 16 + lm_rowb) * ASTR
                                                    + s * 16 + lm_kb) * 2);
                    b[2 * p][0] = t4[0]; b[2 * p][1] = t4[1];
                    b[2 * p + 1][0] = t4[2]; b[2 * p + 1][1] = t4[3];
                }
#pragma unroll
                for (int mi = 0; mi < 2; mi++)
#pragma unroll
                    for (int ni = 0; ni < 8; ni++)
                        mma_f16(acc[mi][ni], a[mi], b[ni]);
            }
        }

        // Epilogue (no smem use — overlaps next job's prologue loads)
#pragma unroll
        for (int mi = 0; mi < 2; mi++) {
#pragma unroll
            for (int half = 0; half < 2; half++) {
                const int m = m0 + wm * 32 + mi * 16 + grp + half * 8;
                if (m >= M) continue;
                int b_idx = 0, itok = 0;
                if (MODE == 0) { b_idx = m / NN; itok = m - b_idx * NN; }
#pragma unroll
                for (int ni = 0; ni < 8; ni++) {
                    const float2 cv = (half == 0)
                        ? make_float2(acc[mi][ni].x, acc[mi][ni].y)
                        : make_float2(acc[mi][ni].z, acc[mi][ni].w);
                    const int n = n0 + wn * 64 + ni * 8 + qid * 2;
                    const float v0 = cv.x + bias[n];
                    const float v1 = cv.y + bias[n + 1];
                    if (MODE == 1) {
                        *(float2*)&Cout[(size_t)m * Nn + n] = make_float2(v0, v1);
                    } else {
                        const int which = n >> 10;      // 0=q 1=k 2=v
                        const int c = n & 1023;
                        const int h = c >> 6;
                        const int d = c & 63;
                        __half* gdst = (which == 0) ? g_qh : (which == 1) ? g_kh : g_vh;
                        const float sc = (which == 0) ? QSCALE : 1.f;
                        __half2* dst = (__half2*)&gdst[((size_t)(b_idx * HH + h) * NN + itok) * HD + d];
                        *dst = __floats2half2_rn(v0 * sc, v1 * sc);
                    }
                }
            }
        }
    }
}

// ---------------------------------------------------------------------------
// Fused attention kernel:
//   blocks [0, 1024): divided spatial attention (fp16 TC, register softmax)
//   blocks [1024, 1088): cls-token attention (one block per (b,h))
// The two are independent (disjoint g_attnh regions); fusing lets cls's 64
// blocks fill divided's partial last wave instead of serializing.
// ---------------------------------------------------------------------------
#define QSTRH 72
#define KSTRH 72
#define VSTRH 216
#define PSTRH 216
#define KP    208

#define OFF_Q  0
#define OFF_K  (OFF_Q + 64 * QSTRH * 2)          // 9216
#define OFF_V  (OFF_K + KP * KSTRH * 2)          // 39168
#define OFF_P  (OFF_V + 64 * VSTRH * 2)          // 66816
#define OFF_R  (OFF_P + 64 * PSTRH * 2)          // 94464  (redM[2][64], redS[2][64])
#define OFF_M  (OFF_R + 4 * 64 * 4)              // 95488  (mask, 212 floats)
#define DIV4_SMEM_BYTES (OFF_M + 212 * 4)        // 96336

__global__ void __launch_bounds__(256, 2)
attn_fused_kernel(const int* __restrict__ tok_mask)
{
    extern __shared__ __align__(16) uint8_t dsm[];
    const int tid = threadIdx.x;

    if (blockIdx.x >= BH * FF) {
        // ---------------- cls-token attention ----------------
        float* qs   = (float*)dsm;                    // 64
        float* p    = qs + 64;                        // NN
        float* red  = p + NN;                         // 256
        float* part = red + 256;                      // 256

        const int bh = blockIdx.x - BH * FF;
        const int b = bh >> 4, h = bh & 15;
        const size_t base = (size_t)bh * NN * HD;

        if (tid < 64) qs[tid] = __half2float(g_qh[base + tid]);
        __syncthreads();

        float mx = -1e30f;
        for (int j = tid; j < NN; j += 256) {
            const __half2* kr = (const __half2*)&g_kh[base + (size_t)j * HD];
            float acc = 0.f;
#pragma unroll
            for (int d2 = 0; d2 < 32; d2++) {
                const float2 kv = __half22float2(kr[d2]);
                acc = fmaf(qs[2 * d2], kv.x, acc);
                acc = fmaf(qs[2 * d2 + 1], kv.y, acc);
            }
            if (!tok_mask[b * NN + j]) acc = -1e30f;
            p[j] = acc;
            mx = fmaxf(mx, acc);
        }
        red[tid] = mx;
        __syncthreads();
        for (int s = 128; s; s >>= 1) {
            if (tid < s) red[tid] = fmaxf(red[tid], red[tid + s]);
            __syncthreads();
        }
        mx = red[0];
        __syncthreads();

        float sum = 0.f;
        for (int j = tid; j < NN; j += 256) {
            const float e = __expf(p[j] - mx);
            p[j] = e;
            sum += e;
        }
        red[tid] = sum;
        __syncthreads();
        for (int s = 128; s; s >>= 1) {
            if (tid < s) red[tid] += red[tid + s];
            __syncthreads();
        }
        const float inv = 1.f / red[0];

        const int pt = tid >> 6;
        const int d = tid & 63;
        float acc = 0.f;
        for (int j = pt; j < NN; j += 4)
            acc = fmaf(p[j], __half2float(g_vh[base + (size_t)j * HD + d]), acc);
        part[pt * 64 + d] = acc;
        __syncthreads();
        if (tid < 64) {
            const float o = (part[tid] + part[64 + tid] + part[128 + tid] + part[192 + tid]) * inv;
            g_attnh[(size_t)b * NN * DIM + (size_t)h * HD + tid] = __float2half_rn(o);
        }
        return;
    }

    // ---------------- divided spatial attention ----------------
    __half2* Qh2 = (__half2*)(dsm + OFF_Q);
    __half2* Kh2 = (__half2*)(dsm + OFF_K);
    __half*  Vh  = (__half*)(dsm + OFF_V);
    __half*  Ph  = (__half*)(dsm + OFF_P);
    float*   redM = (float*)(dsm + OFF_R);           // [2][64]
    float*   redS = (float*)(dsm + OFF_R + 512);     // [2][64]
    float*   Ms  = (float*)(dsm + OFF_M);
    const uint32_t sb = (uint32_t)__cvta_generic_to_shared(dsm);

    const int g = blockIdx.x;
    const int bh = g >> 4, fi = g & 15;
    const int b = bh >> 4, h = bh & 15;
    const int warp = tid >> 5, lane = tid & 31;
    const int grp = lane >> 2, qid = lane & 3;
    const int rw = warp >> 1;                // rows rw*16
    const int chv = warp & 1;                // col half

    const int lm_row16 = lane & 15;
    const int lm_ka    = (lane >> 4) << 3;
    const int lm_rowb  = ((lane >> 4) << 3) + (lane & 7);
    const int lm_kb    = ((lane >> 3) & 1) << 3;

    const size_t base = (size_t)bh * NN * HD;

    // Stage K (row-major, half2) and V (transposed, scalar)
    for (int idx = tid; idx < 197 * 32; idx += 256) {
        const int j = idx >> 5, d2 = idx & 31;
        const int tk = (j == 0) ? 0 : (1 + fi * NS + j - 1);
        Kh2[j * (KSTRH / 2) + d2] = ((const __half2*)&g_kh[base + (size_t)tk * HD])[d2];
    }
    for (int idx = tid; idx < 197 * 64; idx += 256) {
        const int j = idx >> 6, d = idx & 63;
        const int tk = (j == 0) ? 0 : (1 + fi * NS + j - 1);
        Vh[d * VSTRH + j] = g_vh[base + (size_t)tk * HD + d];
    }
    // zero pads
    for (int idx = tid; idx < (KP - 197) * (KSTRH / 2); idx += 256)
        Kh2[197 * (KSTRH / 2) + idx] = __floats2half2_rn(0.f, 0.f);
    for (int idx = tid; idx < 64 * (VSTRH - 197); idx += 256) {
        const int d = idx / (VSTRH - 197);
        const int j = 197 + idx % (VSTRH - 197);
        Vh[d * VSTRH + j] = __float2half_rn(0.f);
    }
    for (int j = tid; j < 212; j += 256) {
        if (j < 197) {
            const int tk = (j == 0) ? 0 : (1 + fi * NS + j - 1);
            Ms[j] = tok_mask[b * NN + tk] ? 0.f : -1e30f;
        } else {
            Ms[j] = -1e30f;
        }
    }

    const int r0 = rw * 16;
    const int rowA = r0 + grp, rowB = r0 + 8 + grp;

#pragma unroll 1
    for (int c = 0; c < 4; c++) {
        const int rb = c * 64;
        const int cnt = min(64, NS - rb);
        __syncthreads();   // previous chunk fully consumed Qh/Ph

        // Load Q chunk (rows >= cnt zeroed)
        for (int idx = tid; idx < 64 * 32; idx += 256) {
            const int i = idx >> 5, d2 = idx & 31;
            Qh2[i * (QSTRH / 2) + d2] = (i < cnt)
                ? ((const __half2*)&g_qh[base + (size_t)(1 + fi * NS + rb + i) * HD])[d2]
                : __floats2half2_rn(0.f, 0.f);
        }
        __syncthreads();

        // S = Q K^T  (registers only; warp: 16 rows x 104 cols = 13 n8 tiles)
        float4 sacc[13];
#pragma unroll
        for (int t = 0; t < 13; t++) sacc[t] = make_float4(0.f, 0.f, 0.f, 0.f);
#pragma unroll
        for (int s = 0; s < 4; s++) {
            uint32_t a[4];
            ldmatrix_x4(a, sb + OFF_Q + (uint32_t)((r0 + lm_row16) * QSTRH + s * 16 + lm_ka) * 2);
#pragma unroll
            for (int p = 0; p < 6; p++) {
                uint32_t t4[4];
                ldmatrix_x4(t4, sb + OFF_K + (uint32_t)((chv * 104 + p * 16 + lm_rowb) * KSTRH
                                                        + s * 16 + lm_kb) * 2);
                uint32_t b0[2] = {t4[0], t4[1]};
                uint32_t b1[2] = {t4[2], t4[3]};
                mma_f16(sacc[2 * p], a, b0);
                mma_f16(sacc[2 * p + 1], a, b1);
            }
            {
                uint32_t t2[2];
                ldmatrix_x2(t2, sb + OFF_K + (uint32_t)((chv * 104 + 96 + (lane & 7)) * KSTRH
                                                        + s * 16 + lm_kb) * 2);
                mma_f16(sacc[12], a, t2);
            }
        }

        // Add mask; row-half max in registers
        float rmax0 = -1e30f, rmax1 = -1e30f;
#pragma unroll
        for (int t = 0; t < 13; t++) {
            const int col = chv * 104 + t * 8 + qid * 2;
            const float2 mv = *(const float2*)&Ms[col];
            sacc[t].x += mv.x; sacc[t].y += mv.y;
            sacc[t].z += mv.x; sacc[t].w += mv.y;
            rmax0 = fmaxf(rmax0, fmaxf(sacc[t].x, sacc[t].y));
            rmax1 = fmaxf(rmax1, fmaxf(sacc[t].z, sacc[t].w));
        }
        rmax0 = fmaxf(rmax0, __shfl_xor_sync(~0u, rmax0, 1));
        rmax0 = fmaxf(rmax0, __shfl_xor_sync(~0u, rmax0, 2));
        rmax1 = fmaxf(rmax1, __shfl_xor_sync(~0u, rmax1, 1));
        rmax1 = fmaxf(rmax1, __shfl_xor_sync(~0u, rmax1, 2));
        if (qid == 0) {
            redM[chv * 64 + rowA] = rmax0;
            redM[chv * 64 + rowB] = rmax1;
        }
        __syncthreads();
        const float m0 = fmaxf(redM[rowA], redM[64 + rowA]);
        const float m1 = fmaxf(redM[rowB], redM[64 + rowB]);

        // exp + row-half sum
        float s0 = 0.f, s1 = 0.f;
#pragma unroll
        for (int t = 0; t < 13; t++) {
            sacc[t].x = __expf(sacc[t].x - m0);
            sacc[t].y = __expf(sacc[t].y - m0);
            sacc[t].z = __expf(sacc[t].z - m1);
            sacc[t].w = __expf(sacc[t].w - m1);
            s0 += sacc[t].x + sacc[t].y;
            s1 += sacc[t].z + sacc[t].w;
        }
        s0 += __shfl_xor_sync(~0u, s0, 1); s0 += __shfl_xor_sync(~0u, s0, 2);
        s1 += __shfl_xor_sync(~0u, s1, 1); s1 += __shfl_xor_sync(~0u, s1, 2);
        if (qid == 0) {
            redS[chv * 64 + rowA] = s0;
            redS[chv * 64 + rowB] = s1;
        }
        __syncthreads();
        const float inv0 = 1.f / (redS[rowA] + redS[64 + rowA]);
        const float inv1 = 1.f / (redS[rowB] + redS[64 + rowB]);

        // P -> fp16 smem (pad cols are exact zeros via exp underflow)
#pragma unroll
        for (int t = 0; t < 13; t++) {
            const int col = chv * 104 + t * 8 + qid * 2;
            *(__half2*)&Ph[rowA * PSTRH + col] = __floats2half2_rn(sacc[t].x * inv0, sacc[t].y * inv0);
            *(__half2*)&Ph[rowB * PSTRH + col] = __floats2half2_rn(sacc[t].z * inv1, sacc[t].w * inv1);
        }
        __syncthreads();

        // O = P V  (64 x 64; warp: 16 rows x 32 cols = 4 n8 tiles, 13 k16 steps)
        float4 oacc[4];
#pragma unroll
        for (int t = 0; t < 4; t++) oacc[t] = make_float4(0.f, 0.f, 0.f, 0.f);
#pragma unroll 1
        for (int s = 0; s < 13; s++) {
            uint32_t a[4];
            ldmatrix_x4(a, sb + OFF_P + (uint32_t)((r0 + lm_row16) * PSTRH + s * 16 + lm_ka) * 2);
#pragma unroll
            for (int p = 0; p < 2; p++) {
                uint32_t t4[4];
                ldmatrix_x4(t4, sb + OFF_V + (uint32_t)((chv * 32 + p * 16 + lm_rowb) * VSTRH
                                                        + s * 16 + lm_kb) * 2);
                uint32_t b0[2] = {t4[0], t4[1]};
                uint32_t b1[2] = {t4[2], t4[3]};
                mma_f16(oacc[2 * p], a, b0);
                mma_f16(oacc[2 * p + 1], a, b1);
            }
        }
        // Epilogue: write fp16 into assembled (B, N, DIM) layout
#pragma unroll
        for (int half = 0; half < 2; half++) {
            const int row = r0 + grp + half * 8;
            if (rb + row < NS) {
                __half* dst = &g_attnh[(size_t)b * NN * DIM
                                       + (size_t)(1 + fi * NS + rb + row) * DIM + h * HD];
#pragma unroll
                for (int t = 0; t < 4; t++) {
                    const int col = chv * 32 + t * 8 + qid * 2;
                    const float2 v = half ? make_float2(oacc[t].z, oacc[t].w)
                                          : make_float2(oacc[t].x, oacc[t].y);
                    *(__half2*)&dst[col] = __floats2half2_rn(v.x, v.y);
                }
            }
        }
    }
}

// ---------------------------------------------------------------------------
extern "C" void kernel_launch(void* const* d_in, const int* in_sizes, int n_in,
                              void* d_out, int out_size)
{
    const float* x      = (const float*)d_in[0];
    const float* qkv_w  = (const float*)d_in[1];
    const float* qkv_b  = (const float*)d_in[2];
    const float* proj_w = (const float*)d_in[3];
    const float* proj_b = (const float*)d_in[4];
    const int*   tmask  = (const int*)d_in[5];
    float* out = (float*)d_out;

    cudaFuncSetAttribute((const void*)gemm_fp16_kernel<0>,
                         cudaFuncAttributeMaxDynamicSharedMemorySize, GSMEM);
    cudaFuncSetAttribute((const void*)gemm_fp16_kernel<1>,
                         cudaFuncAttributeMaxDynamicSharedMemorySize, GSMEM);
    cudaFuncSetAttribute((const void*)attn_fused_kernel,
                         cudaFuncAttributeMaxDynamicSharedMemorySize, DIV4_SMEM_BYTES);

    // 0) fp32 -> fp16 conversion of all GEMM operands (one launch)
    {
        const int n8tot = N8X + N8Q + N8P;
        cvt_all_kernel<<<(n8tot + 255) / 256, 256>>>(x, qkv_w, proj_w);
    }

    // 1) QKV GEMM (persistent, fp16 mma + ldmatrix, 4-stage cp.async)
    {
        const int ntn = 3 * DIM / 128;                  // 24
        const int njobs = ntn * ((M_TOT + 127) / 128);  // 24*99
        gemm_fp16_kernel<0><<<NSM2, 256, GSMEM>>>(qkv_b, nullptr, M_TOT, 3 * DIM, DIM,
                                                  njobs, ntn);
    }

    // 2+3) fused cls + divided spatial attention
    attn_fused_kernel<<<BH * FF + BH, 256, DIV4_SMEM_BYTES>>>(tmask);

    // 4) output projection GEMM (persistent)
    {
        const int ntn = DIM / 128;                      // 8
        const int njobs = ntn * ((M_TOT + 127) / 128);  // 8*99
        gemm_fp16_kernel<1><<<NSM2, 256, GSMEM>>>(proj_b, out, M_TOT, DIM, DIM,
                                                  njobs, ntn);
    }
}

// round 14
// speedup vs baseline: 1.0215x; 1.0215x over previous
#include <cuda_runtime.h>
#include <cuda_fp16.h>
#include <cstdint>

// Problem constants (fixed shapes from reference setup_inputs)
#define BB 4
#define NN 3137          // 1 + 16*196
#define DIM 1024
#define HH 16
#define HD 64
#define FF 16
#define NS 196
#define BH (BB*HH)       // 64
#define M_TOT (BB*NN)    // 12548
#define QSCALE 0.125f    // 64^-0.5

// Scratch in device globals (no allocations allowed)
__device__ __half g_xh[(size_t)M_TOT * DIM];         // fp16 copy of x
__device__ __half g_wqkvh[(size_t)3 * DIM * DIM];    // fp16 qkv_w
__device__ __half g_wprojh[(size_t)DIM * DIM];       // fp16 proj_w
__device__ __half g_qh[(size_t)BH * NN * HD];        // head-major, pre-scaled
__device__ __half g_kh[(size_t)BH * NN * HD];
__device__ __half g_vh[(size_t)BH * NN * HD];
__device__ __half g_attnh[(size_t)BB * NN * DIM];    // (B, N, H*HD) attention out

// ---------------- helpers ----------------
__device__ __forceinline__ void mma_f16(float4& c, const uint32_t a[4], const uint32_t b[2]) {
    asm volatile(
        "mma.sync.aligned.m16n8k16.row.col.f32.f16.f16.f32 "
        "{%0,%1,%2,%3}, {%4,%5,%6,%7}, {%8,%9}, {%0,%1,%2,%3};"
        : "+f"(c.x), "+f"(c.y), "+f"(c.z), "+f"(c.w)
        : "r"(a[0]), "r"(a[1]), "r"(a[2]), "r"(a[3]), "r"(b[0]), "r"(b[1]));
}

__device__ __forceinline__ void ldmatrix_x4(uint32_t* r, uint32_t addr) {
    asm volatile("ldmatrix.sync.aligned.m8n8.x4.shared.b16 {%0,%1,%2,%3}, [%4];"
                 : "=r"(r[0]), "=r"(r[1]), "=r"(r[2]), "=r"(r[3]) : "r"(addr));
}
__device__ __forceinline__ void ldmatrix_x2(uint32_t* r, uint32_t addr) {
    asm volatile("ldmatrix.sync.aligned.m8n8.x2.shared.b16 {%0,%1}, [%2];"
                 : "=r"(r[0]), "=r"(r[1]) : "r"(addr));
}

__device__ __forceinline__ void cp_async16(uint32_t dst_smem, const void* src, int src_bytes) {
    asm volatile("cp.async.cg.shared.global [%0], [%1], 16, %2;"
                 :: "r"(dst_smem), "l"(src), "r"(src_bytes));
}
__device__ __forceinline__ void cp_commit() {
    asm volatile("cp.async.commit_group;");
}
template <int N>
__device__ __forceinline__ void cp_wait() {
    asm volatile("cp.async.wait_group %0;" :: "n"(N));
}

// ---------------------------------------------------------------------------
// fp32 -> fp16 conversion, all three operand arrays in one launch.
// ---------------------------------------------------------------------------
#define N8X (M_TOT * DIM / 8)
#define N8Q (3 * DIM * DIM / 8)
#define N8P (DIM * DIM / 8)

__global__ void __launch_bounds__(256)
cvt_all_kernel(const float* __restrict__ x, const float* __restrict__ wq,
               const float* __restrict__ wp)
{
    const int i = blockIdx.x * blockDim.x + threadIdx.x;
    const float* src;
    __half* dst;
    int off;
    if (i < N8X) {
        dst = g_xh; src = x; off = i;
    } else if (i < N8X + N8Q) {
        dst = g_wqkvh; src = wq; off = i - N8X;
    } else if (i < N8X + N8Q + N8P) {
        dst = g_wprojh; src = wp; off = i - N8X - N8Q;
    } else {
        return;
    }
    const float4 a = ((const float4*)src)[off * 2];
    const float4 b = ((const float4*)src)[off * 2 + 1];
    __half2 h[4];
    h[0] = __floats2half2_rn(a.x, a.y);
    h[1] = __floats2half2_rn(a.z, a.w);
    h[2] = __floats2half2_rn(b.x, b.y);
    h[3] = __floats2half2_rn(b.z, b.w);
    ((uint4*)dst)[off] = *(uint4*)h;
}

// ---------------------------------------------------------------------------
// fp16 tensor-core GEMM, BK=32, 4-stage cp.async, ldmatrix fragment loads.
// Static grid (one CTA per 128x128 output tile). Known-good R10 shape:
// prefetch distance 3 < 4 stages -> no WAR race.
// C[m,n] = sum_k A[m,k] * W[n,k] + bias[n]
// MODE 0: A = g_xh, W = g_wqkvh; epilogue scatters fp16 into g_qh/g_kh/g_vh
// MODE 1: A = g_attnh, W = g_wprojh; epilogue writes fp32 Cout + bias
// Smem: halves, row stride 40 (ldmatrix conflict-free).
// ---------------------------------------------------------------------------
#define ASTR 40
#define TILEH (128 * ASTR)            // halves per A or B tile
#define STG_BYTES (2 * TILEH * 2)     // A+B per stage (20480)
#define GSMEM (4 * STG_BYTES)         // 81920 B

template <int MODE>
__global__ void __launch_bounds__(256, 2)
gemm_fp16_kernel(const float* __restrict__ bias, float* __restrict__ Cout,
                 int M, int Nn, int K)
{
    extern __shared__ __align__(16) uint8_t dsm[];
    const uint32_t sbase = (uint32_t)__cvta_generic_to_shared(dsm);

    const __half* Ah = (MODE == 1) ? g_attnh : g_xh;
    const __half* Bh = (MODE == 1) ? g_wprojh : g_wqkvh;

    const int n0 = blockIdx.x * 128;
    const int m0 = blockIdx.y * 128;
    const int tid = threadIdx.x;
    const int warp = tid >> 5, lane = tid & 31;
    const int grp = lane >> 2, qid = lane & 3;
    const int wm = warp & 3;       // m offset 32*wm
    const int wn = warp >> 2;      // n offset 64*wn

    // ldmatrix lane-address components
    const int lm_row16 = lane & 15;
    const int lm_ka    = (lane >> 4) << 3;
    const int lm_rowb  = ((lane >> 4) << 3) + (lane & 7);
    const int lm_kb    = ((lane >> 3) & 1) << 3;

    float4 acc[2][8];
#pragma unroll
    for (int i = 0; i < 2; i++)
#pragma unroll
        for (int j = 0; j < 8; j++) acc[i][j] = make_float4(0.f, 0.f, 0.f, 0.f);

    auto load_tile = [&](int t, int stg) {
        const int k0 = t * 32;
        const uint32_t ab = sbase + stg * STG_BYTES;
        const uint32_t bb = ab + TILEH * 2;
#pragma unroll
        for (int i = 0; i < 2; i++) {
            const int c = tid + i * 256;        // 0..511
            const int row = c >> 2, ch = c & 3;
            const int gm = m0 + row;
            const __half* asrc = &Ah[(size_t)((gm < M) ? gm : (M - 1)) * K + k0 + ch * 8];
            cp_async16(ab + (uint32_t)(row * ASTR + ch * 8) * 2, asrc, (gm < M) ? 16 : 0);
            cp_async16(bb + (uint32_t)(row * ASTR + ch * 8) * 2,
                       &Bh[(size_t)(n0 + row) * K + k0 + ch * 8], 16);
        }
        cp_commit();
    };

    const int T = K / 32;
    load_tile(0, 0);
    load_tile(1, 1);
    load_tile(2, 2);

    for (int t = 0; t < T; t++) {
        if (t + 2 < T)      cp_wait<2>();
        else if (t + 1 < T) cp_wait<1>();
        else                cp_wait<0>();
        __syncthreads();                 // tile t visible; stage (t+3)%4 consumed
        if (t + 3 < T) load_tile(t + 3, (t + 3) & 3);

        const uint32_t ab = sbase + (t & 3) * STG_BYTES;
        const uint32_t bb = ab + TILEH * 2;
#pragma unroll
        for (int s = 0; s < 2; s++) {
            uint32_t a[2][4];
#pragma unroll
            for (int mi = 0; mi < 2; mi++)
                ldmatrix_x4(a[mi], ab + (uint32_t)((wm * 32 + mi * 16 + lm_row16) * ASTR
                                                   + s * 16 + lm_ka) * 2);
            uint32_t b[8][2];
#pragma unroll
            for (int p = 0; p < 4; p++) {
                uint32_t t4[4];
                ldmatrix_x4(t4, bb + (uint32_t)((wn * 64 + p * 16 + lm_rowb) * ASTR
                                                + s * 16 + lm_kb) * 2);
                b[2 * p][0] = t4[0]; b[2 * p][1] = t4[1];
                b[2 * p + 1][0] = t4[2]; b[2 * p + 1][1] = t4[3];
            }
#pragma unroll
            for (int mi = 0; mi < 2; mi++)
#pragma unroll
                for (int ni = 0; ni < 8; ni++)
                    mma_f16(acc[mi][ni], a[mi], b[ni]);
        }
    }

    // Epilogue: c.x=(r,c) c.y=(r,c+1) c.z=(r+8,c) c.w=(r+8,c+1)
#pragma unroll
    for (int mi = 0; mi < 2; mi++) {
#pragma unroll
        for (int half = 0; half < 2; half++) {
            const int m = m0 + wm * 32 + mi * 16 + grp + half * 8;
            if (m >= M) continue;
            int b_idx = 0, itok = 0;
            if (MODE == 0) { b_idx = m / NN; itok = m - b_idx * NN; }
#pragma unroll
            for (int ni = 0; ni < 8; ni++) {
                const float2 cv = (half == 0)
                    ? make_float2(acc[mi][ni].x, acc[mi][ni].y)
                    : make_float2(acc[mi][ni].z, acc[mi][ni].w);
                const int n = n0 + wn * 64 + ni * 8 + qid * 2;
                const float v0 = cv.x + bias[n];
                const float v1 = cv.y + bias[n + 1];
                if (MODE == 1) {
                    *(float2*)&Cout[(size_t)m * Nn + n] = make_float2(v0, v1);
                } else {
                    const int which = n >> 10;      // 0=q 1=k 2=v
                    const int c = n & 1023;
                    const int h = c >> 6;
                    const int d = c & 63;
                    __half* gdst = (which == 0) ? g_qh : (which == 1) ? g_kh : g_vh;
                    const float sc = (which == 0) ? QSCALE : 1.f;
                    __half2* dst = (__half2*)&gdst[((size_t)(b_idx * HH + h) * NN + itok) * HD + d];
                    *dst = __floats2half2_rn(v0 * sc, v1 * sc);
                }
            }
        }
    }
}

// ---------------------------------------------------------------------------
// Fused attention kernel:
//   blocks [0, 1024): divided spatial attention (fp16 TC, register softmax)
//   blocks [1024, 1088): cls-token attention (one block per (b,h))
// ---------------------------------------------------------------------------
#define QSTRH 72
#define KSTRH 72
#define VSTRH 216
#define PSTRH 216
#define KP    208

#define OFF_Q  0
#define OFF_K  (OFF_Q + 64 * QSTRH * 2)          // 9216
#define OFF_V  (OFF_K + KP * KSTRH * 2)          // 39168
#define OFF_P  (OFF_V + 64 * VSTRH * 2)          // 66816
#define OFF_R  (OFF_P + 64 * PSTRH * 2)          // 94464  (redM[2][64], redS[2][64])
#define OFF_M  (OFF_R + 4 * 64 * 4)              // 95488  (mask, 212 floats)
#define DIV4_SMEM_BYTES (OFF_M + 212 * 4)        // 96336

__global__ void __launch_bounds__(256, 2)
attn_fused_kernel(const int* __restrict__ tok_mask)
{
    extern __shared__ __align__(16) uint8_t dsm[];
    const int tid = threadIdx.x;

    if (blockIdx.x >= BH * FF) {
        // ---------------- cls-token attention ----------------
        float* qs   = (float*)dsm;                    // 64
        float* p    = qs + 64;                        // NN
        float* red  = p + NN;                         // 256
        float* part = red + 256;                      // 256

        const int bh = blockIdx.x - BH * FF;
        const int b = bh >> 4, h = bh & 15;
        const size_t base = (size_t)bh * NN * HD;

        if (tid < 64) qs[tid] = __half2float(g_qh[base + tid]);
        __syncthreads();

        float mx = -1e30f;
        for (int j = tid; j < NN; j += 256) {
            const __half2* kr = (const __half2*)&g_kh[base + (size_t)j * HD];
            float acc = 0.f;
#pragma unroll
            for (int d2 = 0; d2 < 32; d2++) {
                const float2 kv = __half22float2(kr[d2]);
                acc = fmaf(qs[2 * d2], kv.x, acc);
                acc = fmaf(qs[2 * d2 + 1], kv.y, acc);
            }
            if (!tok_mask[b * NN + j]) acc = -1e30f;
            p[j] = acc;
            mx = fmaxf(mx, acc);
        }
        red[tid] = mx;
        __syncthreads();
        for (int s = 128; s; s >>= 1) {
            if (tid < s) red[tid] = fmaxf(red[tid], red[tid + s]);
            __syncthreads();
        }
        mx = red[0];
        __syncthreads();

        float sum = 0.f;
        for (int j = tid; j < NN; j += 256) {
            const float e = __expf(p[j] - mx);
            p[j] = e;
            sum += e;
        }
        red[tid] = sum;
        __syncthreads();
        for (int s = 128; s; s >>= 1) {
            if (tid < s) red[tid] += red[tid + s];
            __syncthreads();
        }
        const float inv = 1.f / red[0];

        const int pt = tid >> 6;
        const int d = tid & 63;
        float acc = 0.f;
        for (int j = pt; j < NN; j += 4)
            acc = fmaf(p[j], __half2float(g_vh[base + (size_t)j * HD + d]), acc);
        part[pt * 64 + d] = acc;
        __syncthreads();
        if (tid < 64) {
            const float o = (part[tid] + part[64 + tid] + part[128 + tid] + part[192 + tid]) * inv;
            g_attnh[(size_t)b * NN * DIM + (size_t)h * HD + tid] = __float2half_rn(o);
        }
        return;
    }

    // ---------------- divided spatial attention ----------------
    __half2* Qh2 = (__half2*)(dsm + OFF_Q);
    __half2* Kh2 = (__half2*)(dsm + OFF_K);
    __half*  Vh  = (__half*)(dsm + OFF_V);
    __half*  Ph  = (__half*)(dsm + OFF_P);
    float*   redM = (float*)(dsm + OFF_R);           // [2][64]
    float*   redS = (float*)(dsm + OFF_R + 512);     // [2][64]
    float*   Ms  = (float*)(dsm + OFF_M);
    const uint32_t sb = (uint32_t)__cvta_generic_to_shared(dsm);

    const int g = blockIdx.x;
    const int bh = g >> 4, fi = g & 15;
    const int b = bh >> 4, h = bh & 15;
    const int warp = tid >> 5, lane = tid & 31;
    const int grp = lane >> 2, qid = lane & 3;
    const int rw = warp >> 1;                // rows rw*16
    const int chv = warp & 1;                // col half

    const int lm_row16 = lane & 15;
    const int lm_ka    = (lane >> 4) << 3;
    const int lm_rowb  = ((lane >> 4) << 3) + (lane & 7);
    const int lm_kb    = ((lane >> 3) & 1) << 3;

    const size_t base = (size_t)bh * NN * HD;

    // Stage K (row-major, half2) and V (transposed, scalar)
    for (int idx = tid; idx < 197 * 32; idx += 256) {
        const int j = idx >> 5, d2 = idx & 31;
        const int tk = (j == 0) ? 0 : (1 + fi * NS + j - 1);
        Kh2[j * (KSTRH / 2) + d2] = ((const __half2*)&g_kh[base + (size_t)tk * HD])[d2];
    }
    for (int idx = tid; idx < 197 * 64; idx += 256) {
        const int j = idx >> 6, d = idx & 63;
        const int tk = (j == 0) ? 0 : (1 + fi * NS + j - 1);
        Vh[d * VSTRH + j] = g_vh[base + (size_t)tk * HD + d];
    }
    // zero pads
    for (int idx = tid; idx < (KP - 197) * (KSTRH / 2); idx += 256)
        Kh2[197 * (KSTRH / 2) + idx] = __floats2half2_rn(0.f, 0.f);
    for (int idx = tid; idx < 64 * (VSTRH - 197); idx += 256) {
        const int d = idx / (VSTRH - 197);
        const int j = 197 + idx % (VSTRH - 197);
        Vh[d * VSTRH + j] = __float2half_rn(0.f);
    }
    for (int j = tid; j < 212; j += 256) {
        if (j < 197) {
            const int tk = (j == 0) ? 0 : (1 + fi * NS + j - 1);
            Ms[j] = tok_mask[b * NN + tk] ? 0.f : -1e30f;
        } else {
            Ms[j] = -1e30f;
        }
    }

    const int r0 = rw * 16;
    const int rowA = r0 + grp, rowB = r0 + 8 + grp;

#pragma unroll 1
    for (int c = 0; c < 4; c++) {
        const int rb = c * 64;
        const int cnt = min(64, NS - rb);
        __syncthreads();   // previous chunk fully consumed Qh/Ph

        // Load Q chunk (rows >= cnt zeroed)
        for (int idx = tid; idx < 64 * 32; idx += 256) {
            const int i = idx >> 5, d2 = idx & 31;
            Qh2[i * (QSTRH / 2) + d2] = (i < cnt)
                ? ((const __half2*)&g_qh[base + (size_t)(1 + fi * NS + rb + i) * HD])[d2]
                : __floats2half2_rn(0.f, 0.f);
        }
        __syncthreads();

        // S = Q K^T  (registers only; warp: 16 rows x 104 cols = 13 n8 tiles)
        float4 sacc[13];
#pragma unroll
        for (int t = 0; t < 13; t++) sacc[t] = make_float4(0.f, 0.f, 0.f, 0.f);
#pragma unroll
        for (int s = 0; s < 4; s++) {
            uint32_t a[4];
            ldmatrix_x4(a, sb + OFF_Q + (uint32_t)((r0 + lm_row16) * QSTRH + s * 16 + lm_ka) * 2);
#pragma unroll
            for (int p = 0; p < 6; p++) {
                uint32_t t4[4];
                ldmatrix_x4(t4, sb + OFF_K + (uint32_t)((chv * 104 + p * 16 + lm_rowb) * KSTRH
                                                        + s * 16 + lm_kb) * 2);
                uint32_t b0[2] = {t4[0], t4[1]};
                uint32_t b1[2] = {t4[2], t4[3]};
                mma_f16(sacc[2 * p], a, b0);
                mma_f16(sacc[2 * p + 1], a, b1);
            }
            {
                uint32_t t2[2];
                ldmatrix_x2(t2, sb + OFF_K + (uint32_t)((chv * 104 + 96 + (lane & 7)) * KSTRH
                                                        + s * 16 + lm_kb) * 2);
                mma_f16(sacc[12], a, t2);
            }
        }

        // Add mask; row-half max in registers
        float rmax0 = -1e30f, rmax1 = -1e30f;
#pragma unroll
        for (int t = 0; t < 13; t++) {
            const int col = chv * 104 + t * 8 + qid * 2;
            const float2 mv = *(const float2*)&Ms[col];
            sacc[t].x += mv.x; sacc[t].y += mv.y;
            sacc[t].z += mv.x; sacc[t].w += mv.y;
            rmax0 = fmaxf(rmax0, fmaxf(sacc[t].x, sacc[t].y));
            rmax1 = fmaxf(rmax1, fmaxf(sacc[t].z, sacc[t].w));
        }
        rmax0 = fmaxf(rmax0, __shfl_xor_sync(~0u, rmax0, 1));
        rmax0 = fmaxf(rmax0, __shfl_xor_sync(~0u, rmax0, 2));
        rmax1 = fmaxf(rmax1, __shfl_xor_sync(~0u, rmax1, 1));
        rmax1 = fmaxf(rmax1, __shfl_xor_sync(~0u, rmax1, 2));
        if (qid == 0) {
            redM[chv * 64 + rowA] = rmax0;
            redM[chv * 64 + rowB] = rmax1;
        }
        __syncthreads();
        const float m0 = fmaxf(redM[rowA], redM[64 + rowA]);
        const float m1 = fmaxf(redM[rowB], redM[64 + rowB]);

        // exp + row-half sum
        float s0 = 0.f, s1 = 0.f;
#pragma unroll
        for (int t = 0; t < 13; t++) {
            sacc[t].x = __expf(sacc[t].x - m0);
            sacc[t].y = __expf(sacc[t].y - m0);
            sacc[t].z = __expf(sacc[t].z - m1);
            sacc[t].w = __expf(sacc[t].w - m1);
            s0 += sacc[t].x + sacc[t].y;
            s1 += sacc[t].z + sacc[t].w;
        }
        s0 += __shfl_xor_sync(~0u, s0, 1); s0 += __shfl_xor_sync(~0u, s0, 2);
        s1 += __shfl_xor_sync(~0u, s1, 1); s1 += __shfl_xor_sync(~0u, s1, 2);
        if (qid == 0) {
            redS[chv * 64 + rowA] = s0;
            redS[chv * 64 + rowB] = s1;
        }
        __syncthreads();
        const float inv0 = 1.f / (redS[rowA] + redS[64 + rowA]);
        const float inv1 = 1.f / (redS[rowB] + redS[64 + rowB]);

        // P -> fp16 smem (pad cols are exact zeros via exp underflow)
#pragma unroll
        for (int t = 0; t < 13; t++) {
            const int col = chv * 104 + t * 8 + qid * 2;
            *(__half2*)&Ph[rowA * PSTRH + col] = __floats2half2_rn(sacc[t].x * inv0, sacc[t].y * inv0);
            *(__half2*)&Ph[rowB * PSTRH + col] = __floats2half2_rn(sacc[t].z * inv1, sacc[t].w * inv1);
        }
        __syncthreads();

        // O = P V  (64 x 64; warp: 16 rows x 32 cols = 4 n8 tiles, 13 k16 steps)
        float4 oacc[4];
#pragma unroll
        for (int t = 0; t < 4; t++) oacc[t] = make_float4(0.f, 0.f, 0.f, 0.f);
#pragma unroll 1
        for (int s = 0; s < 13; s++) {
            uint32_t a[4];
            ldmatrix_x4(a, sb + OFF_P + (uint32_t)((r0 + lm_row16) * PSTRH + s * 16 + lm_ka) * 2);
#pragma unroll
            for (int p = 0; p < 2; p++) {
                uint32_t t4[4];
                ldmatrix_x4(t4, sb + OFF_V + (uint32_t)((chv * 32 + p * 16 + lm_rowb) * VSTRH
                                                        + s * 16 + lm_kb) * 2);
                uint32_t b0[2] = {t4[0], t4[1]};
                uint32_t b1[2] = {t4[2], t4[3]};
                mma_f16(oacc[2 * p], a, b0);
                mma_f16(oacc[2 * p + 1], a, b1);
            }
        }
        // Epilogue: write fp16 into assembled (B, N, DIM) layout
#pragma unroll
        for (int half = 0; half < 2; half++) {
            const int row = r0 + grp + half * 8;
            if (rb + row < NS) {
                __half* dst = &g_attnh[(size_t)b * NN * DIM
                                       + (size_t)(1 + fi * NS + rb + row) * DIM + h * HD];
#pragma unroll
                for (int t = 0; t < 4; t++) {
                    const int col = chv * 32 + t * 8 + qid * 2;
                    const float2 v = half ? make_float2(oacc[t].z, oacc[t].w)
                                          : make_float2(oacc[t].x, oacc[t].y);
                    *(__half2*)&dst[col] = __floats2half2_rn(v.x, v.y);
                }
            }
        }
    }
}

// ---------------------------------------------------------------------------
extern "C" void kernel_launch(void* const* d_in, const int* in_sizes, int n_in,
                              void* d_out, int out_size)
{
    const float* x      = (const float*)d_in[0];
    const float* qkv_w  = (const float*)d_in[1];
    const float* qkv_b  = (const float*)d_in[2];
    const float* proj_w = (const float*)d_in[3];
    const float* proj_b = (const float*)d_in[4];
    const int*   tmask  = (const int*)d_in[5];
    float* out = (float*)d_out;

    cudaFuncSetAttribute((const void*)gemm_fp16_kernel<0>,
                         cudaFuncAttributeMaxDynamicSharedMemorySize, GSMEM);
    cudaFuncSetAttribute((const void*)gemm_fp16_kernel<1>,
                         cudaFuncAttributeMaxDynamicSharedMemorySize, GSMEM);
    cudaFuncSetAttribute((const void*)attn_fused_kernel,
                         cudaFuncAttributeMaxDynamicSharedMemorySize, DIV4_SMEM_BYTES);

    // 0) fp32 -> fp16 conversion of all GEMM operands (one launch)
    {
        const int n8tot = N8X + N8Q + N8P;
        cvt_all_kernel<<<(n8tot + 255) / 256, 256>>>(x, qkv_w, proj_w);
    }

    // 1) QKV GEMM (static grid, fp16 mma + ldmatrix, 4-stage BK=32)
    gemm_fp16_kernel<0><<<dim3(3 * DIM / 128, (M_TOT + 127) / 128), 256, GSMEM>>>(
        qkv_b, nullptr, M_TOT, 3 * DIM, DIM);

    // 2+3) fused cls + divided spatial attention
    attn_fused_kernel<<<BH * FF + BH, 256, DIV4_SMEM_BYTES>>>(tmask);

    // 4) output projection GEMM (static grid)
    gemm_fp16_kernel<1><<<dim3(DIM / 128, (M_TOT + 127) / 128), 256, GSMEM>>>(
        proj_b, out, M_TOT, DIM, DIM);
}

// round 16
// speedup vs baseline: 1.2288x; 1.2029x over previous
#include <cuda_runtime.h>
#include <cuda_fp16.h>
#include <cstdint>

// Problem constants (fixed shapes from reference setup_inputs)
#define BB 4
#define NN 3137          // 1 + 16*196
#define DIM 1024
#define HH 16
#define HD 64
#define FF 16
#define NS 196
#define BH (BB*HH)       // 64
#define M_TOT (BB*NN)    // 12548
#define QSCALE 0.125f    // 64^-0.5

// Scratch in device globals (no allocations allowed)
__device__ __half g_xh[(size_t)M_TOT * DIM];         // fp16 copy of x
__device__ __half g_wqkvh[(size_t)3 * DIM * DIM];    // fp16 qkv_w
__device__ __half g_wprojh[(size_t)DIM * DIM];       // fp16 proj_w
__device__ __half g_qh[(size_t)BH * NN * HD];        // head-major, pre-scaled
__device__ __half g_kh[(size_t)BH * NN * HD];
__device__ __half g_vh[(size_t)BH * NN * HD];
__device__ __half g_attnh[(size_t)BB * NN * DIM];    // (B, N, H*HD) attention out

// ---------------- helpers ----------------
__device__ __forceinline__ void mma_f16(float4& c, const uint32_t a[4], const uint32_t b[2]) {
    asm volatile(
        "mma.sync.aligned.m16n8k16.row.col.f32.f16.f16.f32 "
        "{%0,%1,%2,%3}, {%4,%5,%6,%7}, {%8,%9}, {%0,%1,%2,%3};"
        : "+f"(c.x), "+f"(c.y), "+f"(c.z), "+f"(c.w)
        : "r"(a[0]), "r"(a[1]), "r"(a[2]), "r"(a[3]), "r"(b[0]), "r"(b[1]));
}

__device__ __forceinline__ void ldmatrix_x4(uint32_t* r, uint32_t addr) {
    asm volatile("ldmatrix.sync.aligned.m8n8.x4.shared.b16 {%0,%1,%2,%3}, [%4];"
                 : "=r"(r[0]), "=r"(r[1]), "=r"(r[2]), "=r"(r[3]) : "r"(addr));
}
__device__ __forceinline__ void ldmatrix_x2(uint32_t* r, uint32_t addr) {
    asm volatile("ldmatrix.sync.aligned.m8n8.x2.shared.b16 {%0,%1}, [%2];"
                 : "=r"(r[0]), "=r"(r[1]) : "r"(addr));
}
__device__ __forceinline__ void ldmatrix_x4_trans(uint32_t* r, uint32_t addr) {
    asm volatile("ldmatrix.sync.aligned.m8n8.x4.trans.shared.b16 {%0,%1,%2,%3}, [%4];"
                 : "=r"(r[0]), "=r"(r[1]), "=r"(r[2]), "=r"(r[3]) : "r"(addr));
}

__device__ __forceinline__ void cp_async16(uint32_t dst_smem, const void* src, int src_bytes) {
    asm volatile("cp.async.cg.shared.global [%0], [%1], 16, %2;"
                 :: "r"(dst_smem), "l"(src), "r"(src_bytes));
}
__device__ __forceinline__ void cp_commit() {
    asm volatile("cp.async.commit_group;");
}
template <int N>
__device__ __forceinline__ void cp_wait() {
    asm volatile("cp.async.wait_group %0;" :: "n"(N));
}

// ---------------------------------------------------------------------------
// fp32 -> fp16 conversion, all three operand arrays in one launch.
// ---------------------------------------------------------------------------
#define N8X (M_TOT * DIM / 8)
#define N8Q (3 * DIM * DIM / 8)
#define N8P (DIM * DIM / 8)

__global__ void __launch_bounds__(256)
cvt_all_kernel(const float* __restrict__ x, const float* __restrict__ wq,
               const float* __restrict__ wp)
{
    const int i = blockIdx.x * blockDim.x + threadIdx.x;
    const float* src;
    __half* dst;
    int off;
    if (i < N8X) {
        dst = g_xh; src = x; off = i;
    } else if (i < N8X + N8Q) {
        dst = g_wqkvh; src = wq; off = i - N8X;
    } else if (i < N8X + N8Q + N8P) {
        dst = g_wprojh; src = wp; off = i - N8X - N8Q;
    } else {
        return;
    }
    const float4 a = ((const float4*)src)[off * 2];
    const float4 b = ((const float4*)src)[off * 2 + 1];
    __half2 h[4];
    h[0] = __floats2half2_rn(a.x, a.y);
    h[1] = __floats2half2_rn(a.z, a.w);
    h[2] = __floats2half2_rn(b.x, b.y);
    h[3] = __floats2half2_rn(b.z, b.w);
    ((uint4*)dst)[off] = *(uint4*)h;
}

// ---------------------------------------------------------------------------
// fp16 tensor-core GEMM, BK=32, 4-stage cp.async, ldmatrix fragment loads.
// Static grid (one CTA per 128x128 output tile). Known-good R10 shape.
// MODE 0: A = g_xh, W = g_wqkvh; epilogue scatters fp16 into g_qh/g_kh/g_vh
// MODE 1: A = g_attnh, W = g_wprojh; epilogue writes fp32 Cout + bias
// ---------------------------------------------------------------------------
#define ASTR 40
#define TILEH (128 * ASTR)            // halves per A or B tile
#define STG_BYTES (2 * TILEH * 2)     // A+B per stage (20480)
#define GSMEM (4 * STG_BYTES)         // 81920 B

template <int MODE>
__global__ void __launch_bounds__(256, 2)
gemm_fp16_kernel(const float* __restrict__ bias, float* __restrict__ Cout,
                 int M, int Nn, int K)
{
    extern __shared__ __align__(16) uint8_t dsm[];
    const uint32_t sbase = (uint32_t)__cvta_generic_to_shared(dsm);

    const __half* Ah = (MODE == 1) ? g_attnh : g_xh;
    const __half* Bh = (MODE == 1) ? g_wprojh : g_wqkvh;

    const int n0 = blockIdx.x * 128;
    const int m0 = blockIdx.y * 128;
    const int tid = threadIdx.x;
    const int warp = tid >> 5, lane = tid & 31;
    const int grp = lane >> 2, qid = lane & 3;
    const int wm = warp & 3;       // m offset 32*wm
    const int wn = warp >> 2;      // n offset 64*wn

    const int lm_row16 = lane & 15;
    const int lm_ka    = (lane >> 4) << 3;
    const int lm_rowb  = ((lane >> 4) << 3) + (lane & 7);
    const int lm_kb    = ((lane >> 3) & 1) << 3;

    float4 acc[2][8];
#pragma unroll
    for (int i = 0; i < 2; i++)
#pragma unroll
        for (int j = 0; j < 8; j++) acc[i][j] = make_float4(0.f, 0.f, 0.f, 0.f);

    auto load_tile = [&](int t, int stg) {
        const int k0 = t * 32;
        const uint32_t ab = sbase + stg * STG_BYTES;
        const uint32_t bb = ab + TILEH * 2;
#pragma unroll
        for (int i = 0; i < 2; i++) {
            const int c = tid + i * 256;        // 0..511
            const int row = c >> 2, ch = c & 3;
            const int gm = m0 + row;
            const __half* asrc = &Ah[(size_t)((gm < M) ? gm : (M - 1)) * K + k0 + ch * 8];
            cp_async16(ab + (uint32_t)(row * ASTR + ch * 8) * 2, asrc, (gm < M) ? 16 : 0);
            cp_async16(bb + (uint32_t)(row * ASTR + ch * 8) * 2,
                       &Bh[(size_t)(n0 + row) * K + k0 + ch * 8], 16);
        }
        cp_commit();
    };

    const int T = K / 32;
    load_tile(0, 0);
    load_tile(1, 1);
    load_tile(2, 2);

    for (int t = 0; t < T; t++) {
        if (t + 2 < T)      cp_wait<2>();
        else if (t + 1 < T) cp_wait<1>();
        else                cp_wait<0>();
        __syncthreads();                 // tile t visible; stage (t+3)%4 consumed
        if (t + 3 < T) load_tile(t + 3, (t + 3) & 3);

        const uint32_t ab = sbase + (t & 3) * STG_BYTES;
        const uint32_t bb = ab + TILEH * 2;
#pragma unroll
        for (int s = 0; s < 2; s++) {
            uint32_t a[2][4];
#pragma unroll
            for (int mi = 0; mi < 2; mi++)
                ldmatrix_x4(a[mi], ab + (uint32_t)((wm * 32 + mi * 16 + lm_row16) * ASTR
                                                   + s * 16 + lm_ka) * 2);
            uint32_t b[8][2];
#pragma unroll
            for (int p = 0; p < 4; p++) {
                uint32_t t4[4];
                ldmatrix_x4(t4, bb + (uint32_t)((wn * 64 + p * 16 + lm_rowb) * ASTR
                                                + s * 16 + lm_kb) * 2);
                b[2 * p][0] = t4[0]; b[2 * p][1] = t4[1];
                b[2 * p + 1][0] = t4[2]; b[2 * p + 1][1] = t4[3];
            }
#pragma unroll
            for (int mi = 0; mi < 2; mi++)
#pragma unroll
                for (int ni = 0; ni < 8; ni++)
                    mma_f16(acc[mi][ni], a[mi], b[ni]);
        }
    }

    // Epilogue
#pragma unroll
    for (int mi = 0; mi < 2; mi++) {
#pragma unroll
        for (int half = 0; half < 2; half++) {
            const int m = m0 + wm * 32 + mi * 16 + grp + half * 8;
            if (m >= M) continue;
            int b_idx = 0, itok = 0;
            if (MODE == 0) { b_idx = m / NN; itok = m - b_idx * NN; }
#pragma unroll
            for (int ni = 0; ni < 8; ni++) {
                const float2 cv = (half == 0)
                    ? make_float2(acc[mi][ni].x, acc[mi][ni].y)
                    : make_float2(acc[mi][ni].z, acc[mi][ni].w);
                const int n = n0 + wn * 64 + ni * 8 + qid * 2;
                const float v0 = cv.x + bias[n];
                const float v1 = cv.y + bias[n + 1];
                if (MODE == 1) {
                    *(float2*)&Cout[(size_t)m * Nn + n] = make_float2(v0, v1);
                } else {
                    const int which = n >> 10;      // 0=q 1=k 2=v
                    const int c = n & 1023;
                    const int h = c >> 6;
                    const int d = c & 63;
                    __half* gdst = (which == 0) ? g_qh : (which == 1) ? g_kh : g_vh;
                    const float sc = (which == 0) ? QSCALE : 1.f;
                    __half2* dst = (__half2*)&gdst[((size_t)(b_idx * HH + h) * NN + itok) * HD + d];
                    *dst = __floats2half2_rn(v0 * sc, v1 * sc);
                }
            }
        }
    }
}

// ---------------------------------------------------------------------------
// Fused attention kernel:
//   blocks [0, 64): cls-token attention (long pole first — starts in wave 1)
//   blocks [64, 64+1024): divided spatial attention
// Divided branch: V stored ROW-MAJOR [j][d] stride 72; PV B-fragments loaded
// with ldmatrix.x4.trans (lane -> row k = s*16+(lane&15), col +8*(lane>>4)).
// Stride-72 rows -> 8-row bank groups {0,4,...,28}: conflict-free.
// ---------------------------------------------------------------------------
#define QSTRH 72
#define KSTRH 72
#define VROWH 72
#define PSTRH 216
#define KP    208

#define OFF_Q  0
#define OFF_K  (OFF_Q + 64 * QSTRH * 2)          // 9216
#define OFF_V  (OFF_K + KP * KSTRH * 2)          // 39168
#define OFF_P  (OFF_V + KP * VROWH * 2)          // 69120
#define OFF_R  (OFF_P + 64 * PSTRH * 2)          // 96768 (redM[2][64], redS[2][64])
#define OFF_M  (OFF_R + 4 * 64 * 4)              // 97792 (mask, 212 floats)
#define DIV5_SMEM_BYTES (OFF_M + 212 * 4)        // 98640

__global__ void __launch_bounds__(256, 2)
attn_fused_kernel(const int* __restrict__ tok_mask)
{
    extern __shared__ __align__(16) uint8_t dsm[];
    const int tid = threadIdx.x;

    if (blockIdx.x < BH) {
        // ---------------- cls-token attention ----------------
        float* qs   = (float*)dsm;                    // 64
        float* p    = qs + 64;                        // NN
        float* red  = p + NN;                         // 256
        float* part = red + 256;                      // 256

        const int bh = blockIdx.x;
        const int b = bh >> 4, h = bh & 15;
        const size_t base = (size_t)bh * NN * HD;

        if (tid < 64) qs[tid] = __half2float(g_qh[base + tid]);
        __syncthreads();

        float mx = -1e30f;
        for (int j = tid; j < NN; j += 256) {
            const __half2* kr = (const __half2*)&g_kh[base + (size_t)j * HD];
            float acc = 0.f;
#pragma unroll
            for (int d2 = 0; d2 < 32; d2++) {
                const float2 kv = __half22float2(kr[d2]);
                acc = fmaf(qs[2 * d2], kv.x, acc);
                acc = fmaf(qs[2 * d2 + 1], kv.y, acc);
            }
            if (!tok_mask[b * NN + j]) acc = -1e30f;
            p[j] = acc;
            mx = fmaxf(mx, acc);
        }
        red[tid] = mx;
        __syncthreads();
        for (int s = 128; s; s >>= 1) {
            if (tid < s) red[tid] = fmaxf(red[tid], red[tid + s]);
            __syncthreads();
        }
        mx = red[0];
        __syncthreads();

        float sum = 0.f;
        for (int j = tid; j < NN; j += 256) {
            const float e = __expf(p[j] - mx);
            p[j] = e;
            sum += e;
        }
        red[tid] = sum;
        __syncthreads();
        for (int s = 128; s; s >>= 1) {
            if (tid < s) red[tid] += red[tid + s];
            __syncthreads();
        }
        const float inv = 1.f / red[0];

        const int pt = tid >> 6;
        const int d = tid & 63;
        float acc = 0.f;
        for (int j = pt; j < NN; j += 4)
            acc = fmaf(p[j], __half2float(g_vh[base + (size_t)j * HD + d]), acc);
        part[pt * 64 + d] = acc;
        __syncthreads();
        if (tid < 64) {
            const float o = (part[tid] + part[64 + tid] + part[128 + tid] + part[192 + tid]) * inv;
            g_attnh[(size_t)b * NN * DIM + (size_t)h * HD + tid] = __float2half_rn(o);
        }
        return;
    }

    // ---------------- divided spatial attention ----------------
    __half2* Qh2 = (__half2*)(dsm + OFF_Q);
    __half2* Kh2 = (__half2*)(dsm + OFF_K);
    __half2* Vh2 = (__half2*)(dsm + OFF_V);          // row-major [j][d], stride 72
    __half*  Ph  = (__half*)(dsm + OFF_P);
    float*   redM = (float*)(dsm + OFF_R);           // [2][64]
    float*   redS = (float*)(dsm + OFF_R + 512);     // [2][64]
    float*   Ms  = (float*)(dsm + OFF_M);
    const uint32_t sb = (uint32_t)__cvta_generic_to_shared(dsm);

    const int g = blockIdx.x - BH;
    const int bh = g >> 4, fi = g & 15;
    const int b = bh >> 4, h = bh & 15;
    const int warp = tid >> 5, lane = tid & 31;
    const int grp = lane >> 2, qid = lane & 3;
    const int rw = warp >> 1;                // rows rw*16
    const int chv = warp & 1;                // col half

    const int lm_row16 = lane & 15;
    const int lm_ka    = (lane >> 4) << 3;
    const int lm_rowb  = ((lane >> 4) << 3) + (lane & 7);
    const int lm_kb    = ((lane >> 3) & 1) << 3;
    const int lm_vn    = (lane >> 4) << 3;   // trans: n offset 0/8

    const size_t base = (size_t)bh * NN * HD;

    // Stage K and V (both row-major, coalesced half2 copies)
    for (int idx = tid; idx < 197 * 32; idx += 256) {
        const int j = idx >> 5, d2 = idx & 31;
        const int tk = (j == 0) ? 0 : (1 + fi * NS + j - 1);
        Kh2[j * (KSTRH / 2) + d2] = ((const __half2*)&g_kh[base + (size_t)tk * HD])[d2];
        Vh2[j * (VROWH / 2) + d2] = ((const __half2*)&g_vh[base + (size_t)tk * HD])[d2];
    }
    // zero pad rows 197..207 of K and V
    for (int idx = tid; idx < (KP - 197) * (KSTRH / 2); idx += 256) {
        Kh2[197 * (KSTRH / 2) + idx] = __floats2half2_rn(0.f, 0.f);
        Vh2[197 * (VROWH / 2) + idx] = __floats2half2_rn(0.f, 0.f);
    }
    for (int j = tid; j < 212; j += 256) {
        if (j < 197) {
            const int tk = (j == 0) ? 0 : (1 + fi * NS + j - 1);
            Ms[j] = tok_mask[b * NN + tk] ? 0.f : -1e30f;
        } else {
            Ms[j] = -1e30f;
        }
    }

    const int r0 = rw * 16;
    const int rowA = r0 + grp, rowB = r0 + 8 + grp;

#pragma unroll 1
    for (int c = 0; c < 4; c++) {
        const int rb = c * 64;
        const int cnt = min(64, NS - rb);
        __syncthreads();   // previous chunk fully consumed Qh/Ph

        // Load Q chunk (rows >= cnt zeroed)
        for (int idx = tid; idx < 64 * 32; idx += 256) {
            const int i = idx >> 5, d2 = idx & 31;
            Qh2[i * (QSTRH / 2) + d2] = (i < cnt)
                ? ((const __half2*)&g_qh[base + (size_t)(1 + fi * NS + rb + i) * HD])[d2]
                : __floats2half2_rn(0.f, 0.f);
        }
        __syncthreads();

        // S = Q K^T  (registers only; warp: 16 rows x 104 cols = 13 n8 tiles)
        float4 sacc[13];
#pragma unroll
        for (int t = 0; t < 13; t++) sacc[t] = make_float4(0.f, 0.f, 0.f, 0.f);
#pragma unroll
        for (int s = 0; s < 4; s++) {
            uint32_t a[4];
            ldmatrix_x4(a, sb + OFF_Q + (uint32_t)((r0 + lm_row16) * QSTRH + s * 16 + lm_ka) * 2);
#pragma unroll
            for (int p = 0; p < 6; p++) {
                uint32_t t4[4];
                ldmatrix_x4(t4, sb + OFF_K + (uint32_t)((chv * 104 + p * 16 + lm_rowb) * KSTRH
                                                        + s * 16 + lm_kb) * 2);
                uint32_t b0[2] = {t4[0], t4[1]};
                uint32_t b1[2] = {t4[2], t4[3]};
                mma_f16(sacc[2 * p], a, b0);
                mma_f16(sacc[2 * p + 1], a, b1);
            }
            {
                uint32_t t2[2];
                ldmatrix_x2(t2, sb + OFF_K + (uint32_t)((chv * 104 + 96 + (lane & 7)) * KSTRH
                                                        + s * 16 + lm_kb) * 2);
                mma_f16(sacc[12], a, t2);
            }
        }

        // Add mask; row-half max in registers
        float rmax0 = -1e30f, rmax1 = -1e30f;
#pragma unroll
        for (int t = 0; t < 13; t++) {
            const int col = chv * 104 + t * 8 + qid * 2;
            const float2 mv = *(const float2*)&Ms[col];
            sacc[t].x += mv.x; sacc[t].y += mv.y;
            sacc[t].z += mv.x; sacc[t].w += mv.y;
            rmax0 = fmaxf(rmax0, fmaxf(sacc[t].x, sacc[t].y));
            rmax1 = fmaxf(rmax1, fmaxf(sacc[t].z, sacc[t].w));
        }
        rmax0 = fmaxf(rmax0, __shfl_xor_sync(~0u, rmax0, 1));
        rmax0 = fmaxf(rmax0, __shfl_xor_sync(~0u, rmax0, 2));
        rmax1 = fmaxf(rmax1, __shfl_xor_sync(~0u, rmax1, 1));
        rmax1 = fmaxf(rmax1, __shfl_xor_sync(~0u, rmax1, 2));
        if (qid == 0) {
            redM[chv * 64 + rowA] = rmax0;
            redM[chv * 64 + rowB] = rmax1;
        }
        __syncthreads();
        const float m0 = fmaxf(redM[rowA], redM[64 + rowA]);
        const float m1 = fmaxf(redM[rowB], redM[64 + rowB]);

        // exp + row-half sum
        float s0 = 0.f, s1 = 0.f;
#pragma unroll
        for (int t = 0; t < 13; t++) {
            sacc[t].x = __expf(sacc[t].x - m0);
            sacc[t].y = __expf(sacc[t].y - m0);
            sacc[t].z = __expf(sacc[t].z - m1);
            sacc[t].w = __expf(sacc[t].w - m1);
            s0 += sacc[t].x + sacc[t].y;
            s1 += sacc[t].z + sacc[t].w;
        }
        s0 += __shfl_xor_sync(~0u, s0, 1); s0 += __shfl_xor_sync(~0u, s0, 2);
        s1 += __shfl_xor_sync(~0u, s1, 1); s1 += __shfl_xor_sync(~0u, s1, 2);
        if (qid == 0) {
            redS[chv * 64 + rowA] = s0;
            redS[chv * 64 + rowB] = s1;
        }
        __syncthreads();
        const float inv0 = 1.f / (redS[rowA] + redS[64 + rowA]);
        const float inv1 = 1.f / (redS[rowB] + redS[64 + rowB]);

        // P -> fp16 smem (pad cols are exact zeros via exp underflow)
#pragma unroll
        for (int t = 0; t < 13; t++) {
            const int col = chv * 104 + t * 8 + qid * 2;
            *(__half2*)&Ph[rowA * PSTRH + col] = __floats2half2_rn(sacc[t].x * inv0, sacc[t].y * inv0);
            *(__half2*)&Ph[rowB * PSTRH + col] = __floats2half2_rn(sacc[t].z * inv1, sacc[t].w * inv1);
        }
        __syncthreads();

        // O = P V  (64 x 64; warp: 16 rows x 32 cols = 4 n8 tiles, 13 k16 steps)
        // B-fragments via ldmatrix.trans from row-major V[j][d].
        float4 oacc[4];
#pragma unroll
        for (int t = 0; t < 4; t++) oacc[t] = make_float4(0.f, 0.f, 0.f, 0.f);
#pragma unroll 1
        for (int s = 0; s < 13; s++) {
            uint32_t a[4];
            ldmatrix_x4(a, sb + OFF_P + (uint32_t)((r0 + lm_row16) * PSTRH + s * 16 + lm_ka) * 2);
#pragma unroll
            for (int p = 0; p < 2; p++) {
                const int d0 = chv * 32 + p * 16;
                uint32_t t4[4];
                ldmatrix_x4_trans(t4, sb + OFF_V
                    + (uint32_t)((s * 16 + lm_row16) * VROWH + d0 + lm_vn) * 2);
                uint32_t b0[2] = {t4[0], t4[1]};
                uint32_t b1[2] = {t4[2], t4[3]};
                mma_f16(oacc[2 * p], a, b0);
                mma_f16(oacc[2 * p + 1], a, b1);
            }
        }
        // Epilogue: write fp16 into assembled (B, N, DIM) layout
#pragma unroll
        for (int half = 0; half < 2; half++) {
            const int row = r0 + grp + half * 8;
            if (rb + row < NS) {
                __half* dst = &g_attnh[(size_t)b * NN * DIM
                                       + (size_t)(1 + fi * NS + rb + row) * DIM + h * HD];
#pragma unroll
                for (int t = 0; t < 4; t++) {
                    const int col = chv * 32 + t * 8 + qid * 2;
                    const float2 v = half ? make_float2(oacc[t].z, oacc[t].w)
                                          : make_float2(oacc[t].x, oacc[t].y);
                    *(__half2*)&dst[col] = __floats2half2_rn(v.x, v.y);
                }
            }
        }
    }
}

// ---------------------------------------------------------------------------
extern "C" void kernel_launch(void* const* d_in, const int* in_sizes, int n_in,
                              void* d_out, int out_size)
{
    const float* x      = (const float*)d_in[0];
    const float* qkv_w  = (const float*)d_in[1];
    const float* qkv_b  = (const float*)d_in[2];
    const float* proj_w = (const float*)d_in[3];
    const float* proj_b = (const float*)d_in[4];
    const int*   tmask  = (const int*)d_in[5];
    float* out = (float*)d_out;

    cudaFuncSetAttribute((const void*)gemm_fp16_kernel<0>,
                         cudaFuncAttributeMaxDynamicSharedMemorySize, GSMEM);
    cudaFuncSetAttribute((const void*)gemm_fp16_kernel<1>,
                         cudaFuncAttributeMaxDynamicSharedMemorySize, GSMEM);
    cudaFuncSetAttribute((const void*)attn_fused_kernel,
                         cudaFuncAttributeMaxDynamicSharedMemorySize, DIV5_SMEM_BYTES);

    // 0) fp32 -> fp16 conversion of all GEMM operands (one launch)
    {
        const int n8tot = N8X + N8Q + N8P;
        cvt_all_kernel<<<(n8tot + 255) / 256, 256>>>(x, qkv_w, proj_w);
    }

    // 1) QKV GEMM (static grid, fp16 mma + ldmatrix, 4-stage BK=32)
    gemm_fp16_kernel<0><<<dim3(3 * DIM / 128, (M_TOT + 127) / 128), 256, GSMEM>>>(
        qkv_b, nullptr, M_TOT, 3 * DIM, DIM);

    // 2+3) fused cls (first) + divided spatial attention
    attn_fused_kernel<<<BH + BH * FF, 256, DIV5_SMEM_BYTES>>>(tmask);

    // 4) output projection GEMM (static grid)
    gemm_fp16_kernel<1><<<dim3(DIM / 128, (M_TOT + 127) / 128), 256, GSMEM>>>(
        proj_b, out, M_TOT, DIM, DIM);
}

// round 17
// speedup vs baseline: 1.2342x; 1.0044x over previous
#include <cuda_runtime.h>
#include <cuda_fp16.h>
#include <cstdint>

// Problem constants (fixed shapes from reference setup_inputs)
#define BB 4
#define NN 3137          // 1 + 16*196
#define DIM 1024
#define HH 16
#define HD 64
#define FF 16
#define NS 196
#define BH (BB*HH)       // 64
#define M_TOT (BB*NN)    // 12548
#define QSCALE 0.125f    // 64^-0.5

// Scratch in device globals (no allocations allowed)
__device__ __half g_xh[(size_t)M_TOT * DIM];         // fp16 copy of x
__device__ __half g_wqkvh[(size_t)3 * DIM * DIM];    // fp16 qkv_w
__device__ __half g_wprojh[(size_t)DIM * DIM];       // fp16 proj_w
__device__ __half g_qh[(size_t)BH * NN * HD];        // head-major, pre-scaled
__device__ __half g_kh[(size_t)BH * NN * HD];
__device__ __half g_vh[(size_t)BH * NN * HD];
__device__ __half g_attnh[(size_t)BB * NN * DIM];    // (B, N, H*HD) attention out

// ---------------- helpers ----------------
__device__ __forceinline__ void mma_f16(float4& c, const uint32_t a[4], const uint32_t b[2]) {
    asm volatile(
        "mma.sync.aligned.m16n8k16.row.col.f32.f16.f16.f32 "
        "{%0,%1,%2,%3}, {%4,%5,%6,%7}, {%8,%9}, {%0,%1,%2,%3};"
        : "+f"(c.x), "+f"(c.y), "+f"(c.z), "+f"(c.w)
        : "r"(a[0]), "r"(a[1]), "r"(a[2]), "r"(a[3]), "r"(b[0]), "r"(b[1]));
}

__device__ __forceinline__ void ldmatrix_x4(uint32_t* r, uint32_t addr) {
    asm volatile("ldmatrix.sync.aligned.m8n8.x4.shared.b16 {%0,%1,%2,%3}, [%4];"
                 : "=r"(r[0]), "=r"(r[1]), "=r"(r[2]), "=r"(r[3]) : "r"(addr));
}
__device__ __forceinline__ void ldmatrix_x2(uint32_t* r, uint32_t addr) {
    asm volatile("ldmatrix.sync.aligned.m8n8.x2.shared.b16 {%0,%1}, [%2];"
                 : "=r"(r[0]), "=r"(r[1]) : "r"(addr));
}
__device__ __forceinline__ void ldmatrix_x4_trans(uint32_t* r, uint32_t addr) {
    asm volatile("ldmatrix.sync.aligned.m8n8.x4.trans.shared.b16 {%0,%1,%2,%3}, [%4];"
                 : "=r"(r[0]), "=r"(r[1]), "=r"(r[2]), "=r"(r[3]) : "r"(addr));
}

__device__ __forceinline__ void cp_async16(uint32_t dst_smem, const void* src, int src_bytes) {
    asm volatile("cp.async.cg.shared.global [%0], [%1], 16, %2;"
                 :: "r"(dst_smem), "l"(src), "r"(src_bytes));
}
__device__ __forceinline__ void cp_commit() {
    asm volatile("cp.async.commit_group;");
}
template <int N>
__device__ __forceinline__ void cp_wait() {
    asm volatile("cp.async.wait_group %0;" :: "n"(N));
}

// ---------------------------------------------------------------------------
// fp32 -> fp16 conversion, all three operand arrays in one launch.
// ---------------------------------------------------------------------------
#define N8X (M_TOT * DIM / 8)
#define N8Q (3 * DIM * DIM / 8)
#define N8P (DIM * DIM / 8)

__global__ void __launch_bounds__(256)
cvt_all_kernel(const float* __restrict__ x, const float* __restrict__ wq,
               const float* __restrict__ wp)
{
    const int i = blockIdx.x * blockDim.x + threadIdx.x;
    const float* src;
    __half* dst;
    int off;
    if (i < N8X) {
        dst = g_xh; src = x; off = i;
    } else if (i < N8X + N8Q) {
        dst = g_wqkvh; src = wq; off = i - N8X;
    } else if (i < N8X + N8Q + N8P) {
        dst = g_wprojh; src = wp; off = i - N8X - N8Q;
    } else {
        return;
    }
    const float4 a = ((const float4*)src)[off * 2];
    const float4 b = ((const float4*)src)[off * 2 + 1];
    __half2 h[4];
    h[0] = __floats2half2_rn(a.x, a.y);
    h[1] = __floats2half2_rn(a.z, a.w);
    h[2] = __floats2half2_rn(b.x, b.y);
    h[3] = __floats2half2_rn(b.z, b.w);
    ((uint4*)dst)[off] = *(uint4*)h;
}

// ---------------------------------------------------------------------------
// fp16 tensor-core GEMM, BK=32, 4-stage cp.async, ldmatrix fragment loads.
// Static grid (one CTA per 128x128 output tile). Known-good R10/R16 shape.
// MODE 0: A = g_xh, W = g_wqkvh; epilogue scatters fp16 into g_qh/g_kh/g_vh
// MODE 1: A = g_attnh, W = g_wprojh; epilogue writes fp32 Cout + bias
// ---------------------------------------------------------------------------
#define ASTR 40
#define TILEH (128 * ASTR)            // halves per A or B tile
#define STG_BYTES (2 * TILEH * 2)     // A+B per stage (20480)
#define GSMEM (4 * STG_BYTES)         // 81920 B

template <int MODE>
__global__ void __launch_bounds__(256, 2)
gemm_fp16_kernel(const float* __restrict__ bias, float* __restrict__ Cout,
                 int M, int Nn, int K)
{
    extern __shared__ __align__(16) uint8_t dsm[];
    const uint32_t sbase = (uint32_t)__cvta_generic_to_shared(dsm);

    const __half* Ah = (MODE == 1) ? g_attnh : g_xh;
    const __half* Bh = (MODE == 1) ? g_wprojh : g_wqkvh;

    const int n0 = blockIdx.x * 128;
    const int m0 = blockIdx.y * 128;
    const int tid = threadIdx.x;
    const int warp = tid >> 5, lane = tid & 31;
    const int grp = lane >> 2, qid = lane & 3;
    const int wm = warp & 3;       // m offset 32*wm
    const int wn = warp >> 2;      // n offset 64*wn

    const int lm_row16 = lane & 15;
    const int lm_ka    = (lane >> 4) << 3;
    const int lm_rowb  = ((lane >> 4) << 3) + (lane & 7);
    const int lm_kb    = ((lane >> 3) & 1) << 3;

    float4 acc[2][8];
#pragma unroll
    for (int i = 0; i < 2; i++)
#pragma unroll
        for (int j = 0; j < 8; j++) acc[i][j] = make_float4(0.f, 0.f, 0.f, 0.f);

    auto load_tile = [&](int t, int stg) {
        const int k0 = t * 32;
        const uint32_t ab = sbase + stg * STG_BYTES;
        const uint32_t bb = ab + TILEH * 2;
#pragma unroll
        for (int i = 0; i < 2; i++) {
            const int c = tid + i * 256;        // 0..511
            const int row = c >> 2, ch = c & 3;
            const int gm = m0 + row;
            const __half* asrc = &Ah[(size_t)((gm < M) ? gm : (M - 1)) * K + k0 + ch * 8];
            cp_async16(ab + (uint32_t)(row * ASTR + ch * 8) * 2, asrc, (gm < M) ? 16 : 0);
            cp_async16(bb + (uint32_t)(row * ASTR + ch * 8) * 2,
                       &Bh[(size_t)(n0 + row) * K + k0 + ch * 8], 16);
        }
        cp_commit();
    };

    const int T = K / 32;
    load_tile(0, 0);
    load_tile(1, 1);
    load_tile(2, 2);

    for (int t = 0; t < T; t++) {
        if (t + 2 < T)      cp_wait<2>();
        else if (t + 1 < T) cp_wait<1>();
        else                cp_wait<0>();
        __syncthreads();                 // tile t visible; stage (t+3)%4 consumed
        if (t + 3 < T) load_tile(t + 3, (t + 3) & 3);

        const uint32_t ab = sbase + (t & 3) * STG_BYTES;
        const uint32_t bb = ab + TILEH * 2;
#pragma unroll
        for (int s = 0; s < 2; s++) {
            uint32_t a[2][4];
#pragma unroll
            for (int mi = 0; mi < 2; mi++)
                ldmatrix_x4(a[mi], ab + (uint32_t)((wm * 32 + mi * 16 + lm_row16) * ASTR
                                                   + s * 16 + lm_ka) * 2);
            uint32_t b[8][2];
#pragma unroll
            for (int p = 0; p < 4; p++) {
                uint32_t t4[4];
                ldmatrix_x4(t4, bb + (uint32_t)((wn * 64 + p * 16 + lm_rowb) * ASTR
                                                + s * 16 + lm_kb) * 2);
                b[2 * p][0] = t4[0]; b[2 * p][1] = t4[1];
                b[2 * p + 1][0] = t4[2]; b[2 * p + 1][1] = t4[3];
            }
#pragma unroll
            for (int mi = 0; mi < 2; mi++)
#pragma unroll
                for (int ni = 0; ni < 8; ni++)
                    mma_f16(acc[mi][ni], a[mi], b[ni]);
        }
    }

    // Epilogue
#pragma unroll
    for (int mi = 0; mi < 2; mi++) {
#pragma unroll
        for (int half = 0; half < 2; half++) {
            const int m = m0 + wm * 32 + mi * 16 + grp + half * 8;
            if (m >= M) continue;
            int b_idx = 0, itok = 0;
            if (MODE == 0) { b_idx = m / NN; itok = m - b_idx * NN; }
#pragma unroll
            for (int ni = 0; ni < 8; ni++) {
                const float2 cv = (half == 0)
                    ? make_float2(acc[mi][ni].x, acc[mi][ni].y)
                    : make_float2(acc[mi][ni].z, acc[mi][ni].w);
                const int n = n0 + wn * 64 + ni * 8 + qid * 2;
                const float v0 = cv.x + bias[n];
                const float v1 = cv.y + bias[n + 1];
                if (MODE == 1) {
                    *(float2*)&Cout[(size_t)m * Nn + n] = make_float2(v0, v1);
                } else {
                    const int which = n >> 10;      // 0=q 1=k 2=v
                    const int c = n & 1023;
                    const int h = c >> 6;
                    const int d = c & 63;
                    __half* gdst = (which == 0) ? g_qh : (which == 1) ? g_kh : g_vh;
                    const float sc = (which == 0) ? QSCALE : 1.f;
                    __half2* dst = (__half2*)&gdst[((size_t)(b_idx * HH + h) * NN + itok) * HD + d];
                    *dst = __floats2half2_rn(v0 * sc, v1 * sc);
                }
            }
        }
    }
}

// ---------------------------------------------------------------------------
// Fused attention kernel:
//   blocks [0, 64): cls-token attention (long pole first — starts in wave 1)
//   blocks [64, 64+1024): divided spatial attention
// Divided: V row-major + ldmatrix.trans (R16, verified); NEW: warp-pairs with
// r0 >= cnt skip the S-MMA/softmax/PV compute entirely (row-disjoint slabs;
// barriers stay unconditional). Saves ~3/4 of chunk 3 (cnt=4) work.
// ---------------------------------------------------------------------------
#define QSTRH 72
#define KSTRH 72
#define VROWH 72
#define PSTRH 216
#define KP    208

#define OFF_Q  0
#define OFF_K  (OFF_Q + 64 * QSTRH * 2)          // 9216
#define OFF_V  (OFF_K + KP * KSTRH * 2)          // 39168
#define OFF_P  (OFF_V + KP * VROWH * 2)          // 69120
#define OFF_R  (OFF_P + 64 * PSTRH * 2)          // 96768 (redM[2][64], redS[2][64])
#define OFF_M  (OFF_R + 4 * 64 * 4)              // 97792 (mask, 212 floats)
#define DIV5_SMEM_BYTES (OFF_M + 212 * 4)        // 98640

__global__ void __launch_bounds__(256, 2)
attn_fused_kernel(const int* __restrict__ tok_mask)
{
    extern __shared__ __align__(16) uint8_t dsm[];
    const int tid = threadIdx.x;

    if (blockIdx.x < BH) {
        // ---------------- cls-token attention ----------------
        float* qs   = (float*)dsm;                    // 64
        float* p    = qs + 64;                        // NN
        float* red  = p + NN;                         // 256
        float* part = red + 256;                      // 256

        const int bh = blockIdx.x;
        const int b = bh >> 4, h = bh & 15;
        const size_t base = (size_t)bh * NN * HD;

        if (tid < 64) qs[tid] = __half2float(g_qh[base + tid]);
        __syncthreads();

        float mx = -1e30f;
        for (int j = tid; j < NN; j += 256) {
            const __half2* kr = (const __half2*)&g_kh[base + (size_t)j * HD];
            float acc = 0.f;
#pragma unroll
            for (int d2 = 0; d2 < 32; d2++) {
                const float2 kv = __half22float2(kr[d2]);
                acc = fmaf(qs[2 * d2], kv.x, acc);
                acc = fmaf(qs[2 * d2 + 1], kv.y, acc);
            }
            if (!tok_mask[b * NN + j]) acc = -1e30f;
            p[j] = acc;
            mx = fmaxf(mx, acc);
        }
        red[tid] = mx;
        __syncthreads();
        for (int s = 128; s; s >>= 1) {
            if (tid < s) red[tid] = fmaxf(red[tid], red[tid + s]);
            __syncthreads();
        }
        mx = red[0];
        __syncthreads();

        float sum = 0.f;
        for (int j = tid; j < NN; j += 256) {
            const float e = __expf(p[j] - mx);
            p[j] = e;
            sum += e;
        }
        red[tid] = sum;
        __syncthreads();
        for (int s = 128; s; s >>= 1) {
            if (tid < s) red[tid] += red[tid + s];
            __syncthreads();
        }
        const float inv = 1.f / red[0];

        const int pt = tid >> 6;
        const int d = tid & 63;
        float acc = 0.f;
        for (int j = pt; j < NN; j += 4)
            acc = fmaf(p[j], __half2float(g_vh[base + (size_t)j * HD + d]), acc);
        part[pt * 64 + d] = acc;
        __syncthreads();
        if (tid < 64) {
            const float o = (part[tid] + part[64 + tid] + part[128 + tid] + part[192 + tid]) * inv;
            g_attnh[(size_t)b * NN * DIM + (size_t)h * HD + tid] = __float2half_rn(o);
        }
        return;
    }

    // ---------------- divided spatial attention ----------------
    __half2* Qh2 = (__half2*)(dsm + OFF_Q);
    __half2* Kh2 = (__half2*)(dsm + OFF_K);
    __half2* Vh2 = (__half2*)(dsm + OFF_V);          // row-major [j][d], stride 72
    __half*  Ph  = (__half*)(dsm + OFF_P);
    float*   redM = (float*)(dsm + OFF_R);           // [2][64]
    float*   redS = (float*)(dsm + OFF_R + 512);     // [2][64]
    float*   Ms  = (float*)(dsm + OFF_M);
    const uint32_t sb = (uint32_t)__cvta_generic_to_shared(dsm);

    const int g = blockIdx.x - BH;
    const int bh = g >> 4, fi = g & 15;
    const int b = bh >> 4, h = bh & 15;
    const int warp = tid >> 5, lane = tid & 31;
    const int grp = lane >> 2, qid = lane & 3;
    const int rw = warp >> 1;                // rows rw*16
    const int chv = warp & 1;                // col half

    const int lm_row16 = lane & 15;
    const int lm_ka    = (lane >> 4) << 3;
    const int lm_rowb  = ((lane >> 4) << 3) + (lane & 7);
    const int lm_kb    = ((lane >> 3) & 1) << 3;
    const int lm_vn    = (lane >> 4) << 3;   // trans: n offset 0/8

    const size_t base = (size_t)bh * NN * HD;

    // Stage K and V (both row-major, coalesced half2 copies)
    for (int idx = tid; idx < 197 * 32; idx += 256) {
        const int j = idx >> 5, d2 = idx & 31;
        const int tk = (j == 0) ? 0 : (1 + fi * NS + j - 1);
        Kh2[j * (KSTRH / 2) + d2] = ((const __half2*)&g_kh[base + (size_t)tk * HD])[d2];
        Vh2[j * (VROWH / 2) + d2] = ((const __half2*)&g_vh[base + (size_t)tk * HD])[d2];
    }
    // zero pad rows 197..207 of K and V
    for (int idx = tid; idx < (KP - 197) * (KSTRH / 2); idx += 256) {
        Kh2[197 * (KSTRH / 2) + idx] = __floats2half2_rn(0.f, 0.f);
        Vh2[197 * (VROWH / 2) + idx] = __floats2half2_rn(0.f, 0.f);
    }
    for (int j = tid; j < 212; j += 256) {
        if (j < 197) {
            const int tk = (j == 0) ? 0 : (1 + fi * NS + j - 1);
            Ms[j] = tok_mask[b * NN + tk] ? 0.f : -1e30f;
        } else {
            Ms[j] = -1e30f;
        }
    }

    const int r0 = rw * 16;
    const int rowA = r0 + grp, rowB = r0 + 8 + grp;

#pragma unroll 1
    for (int c = 0; c < 4; c++) {
        const int rb = c * 64;
        const int cnt = min(64, NS - rb);
        const int cnt16 = (cnt + 15) & ~15;       // rows needed in smem
        const bool act = (r0 < cnt);              // this warp-pair has valid rows
        __syncthreads();   // previous chunk fully consumed Qh/Ph

        // Load Q chunk (only ceil16(cnt) rows; rows >= cnt zeroed)
        for (int idx = tid; idx < cnt16 * 32; idx += 256) {
            const int i = idx >> 5, d2 = idx & 31;
            Qh2[i * (QSTRH / 2) + d2] = (i < cnt)
                ? ((const __half2*)&g_qh[base + (size_t)(1 + fi * NS + rb + i) * HD])[d2]
                : __floats2half2_rn(0.f, 0.f);
        }
        __syncthreads();

        float4 sacc[13];
        if (act) {
            // S = Q K^T  (registers only; warp: 16 rows x 104 cols = 13 n8 tiles)
#pragma unroll
            for (int t = 0; t < 13; t++) sacc[t] = make_float4(0.f, 0.f, 0.f, 0.f);
#pragma unroll
            for (int s = 0; s < 4; s++) {
                uint32_t a[4];
                ldmatrix_x4(a, sb + OFF_Q + (uint32_t)((r0 + lm_row16) * QSTRH + s * 16 + lm_ka) * 2);
#pragma unroll
                for (int p = 0; p < 6; p++) {
                    uint32_t t4[4];
                    ldmatrix_x4(t4, sb + OFF_K + (uint32_t)((chv * 104 + p * 16 + lm_rowb) * KSTRH
                                                            + s * 16 + lm_kb) * 2);
                    uint32_t b0[2] = {t4[0], t4[1]};
                    uint32_t b1[2] = {t4[2], t4[3]};
                    mma_f16(sacc[2 * p], a, b0);
                    mma_f16(sacc[2 * p + 1], a, b1);
                }
                {
                    uint32_t t2[2];
                    ldmatrix_x2(t2, sb + OFF_K + (uint32_t)((chv * 104 + 96 + (lane & 7)) * KSTRH
                                                            + s * 16 + lm_kb) * 2);
                    mma_f16(sacc[12], a, t2);
                }
            }

            // Add mask; row-half max in registers
            float rmax0 = -1e30f, rmax1 = -1e30f;
#pragma unroll
            for (int t = 0; t < 13; t++) {
                const int col = chv * 104 + t * 8 + qid * 2;
                const float2 mv = *(const float2*)&Ms[col];
                sacc[t].x += mv.x; sacc[t].y += mv.y;
                sacc[t].z += mv.x; sacc[t].w += mv.y;
                rmax0 = fmaxf(rmax0, fmaxf(sacc[t].x, sacc[t].y));
                rmax1 = fmaxf(rmax1, fmaxf(sacc[t].z, sacc[t].w));
            }
            rmax0 = fmaxf(rmax0, __shfl_xor_sync(~0u, rmax0, 1));
            rmax0 = fmaxf(rmax0, __shfl_xor_sync(~0u, rmax0, 2));
            rmax1 = fmaxf(rmax1, __shfl_xor_sync(~0u, rmax1, 1));
            rmax1 = fmaxf(rmax1, __shfl_xor_sync(~0u, rmax1, 2));
            if (qid == 0) {
                redM[chv * 64 + rowA] = rmax0;
                redM[chv * 64 + rowB] = rmax1;
            }
        }
        __syncthreads();

        if (act) {
            const float m0 = fmaxf(redM[rowA], redM[64 + rowA]);
            const float m1 = fmaxf(redM[rowB], redM[64 + rowB]);

            // exp + row-half sum
            float s0 = 0.f, s1 = 0.f;
#pragma unroll
            for (int t = 0; t < 13; t++) {
                sacc[t].x = __expf(sacc[t].x - m0);
                sacc[t].y = __expf(sacc[t].y - m0);
                sacc[t].z = __expf(sacc[t].z - m1);
                sacc[t].w = __expf(sacc[t].w - m1);
                s0 += sacc[t].x + sacc[t].y;
                s1 += sacc[t].z + sacc[t].w;
            }
            s0 += __shfl_xor_sync(~0u, s0, 1); s0 += __shfl_xor_sync(~0u, s0, 2);
            s1 += __shfl_xor_sync(~0u, s1, 1); s1 += __shfl_xor_sync(~0u, s1, 2);
            if (qid == 0) {
                redS[chv * 64 + rowA] = s0;
                redS[chv * 64 + rowB] = s1;
            }
        }
        __syncthreads();

        if (act) {
            const float inv0 = 1.f / (redS[rowA] + redS[64 + rowA]);
            const float inv1 = 1.f / (redS[rowB] + redS[64 + rowB]);

            // P -> fp16 smem (pad cols are exact zeros via exp underflow)
#pragma unroll
            for (int t = 0; t < 13; t++) {
                const int col = chv * 104 + t * 8 + qid * 2;
                *(__half2*)&Ph[rowA * PSTRH + col] = __floats2half2_rn(sacc[t].x * inv0, sacc[t].y * inv0);
                *(__half2*)&Ph[rowB * PSTRH + col] = __floats2half2_rn(sacc[t].z * inv1, sacc[t].w * inv1);
            }
        }
        __syncthreads();

        if (act) {
            // O = P V  (warp: 16 rows x 32 cols = 4 n8 tiles, 13 k16 steps)
            // B-fragments via ldmatrix.trans from row-major V[j][d].
            float4 oacc[4];
#pragma unroll
            for (int t = 0; t < 4; t++) oacc[t] = make_float4(0.f, 0.f, 0.f, 0.f);
#pragma unroll 1
            for (int s = 0; s < 13; s++) {
                uint32_t a[4];
                ldmatrix_x4(a, sb + OFF_P + (uint32_t)((r0 + lm_row16) * PSTRH + s * 16 + lm_ka) * 2);
#pragma unroll
                for (int p = 0; p < 2; p++) {
                    const int d0 = chv * 32 + p * 16;
                    uint32_t t4[4];
                    ldmatrix_x4_trans(t4, sb + OFF_V
                        + (uint32_t)((s * 16 + lm_row16) * VROWH + d0 + lm_vn) * 2);
                    uint32_t b0[2] = {t4[0], t4[1]};
                    uint32_t b1[2] = {t4[2], t4[3]};
                    mma_f16(oacc[2 * p], a, b0);
                    mma_f16(oacc[2 * p + 1], a, b1);
                }
            }
            // Epilogue: write fp16 into assembled (B, N, DIM) layout
#pragma unroll
            for (int half = 0; half < 2; half++) {
                const int row = r0 + grp + half * 8;
                if (rb + row < NS) {
                    __half* dst = &g_attnh[(size_t)b * NN * DIM
                                           + (size_t)(1 + fi * NS + rb + row) * DIM + h * HD];
#pragma unroll
                    for (int t = 0; t < 4; t++) {
                        const int col = chv * 32 + t * 8 + qid * 2;
                        const float2 v = half ? make_float2(oacc[t].z, oacc[t].w)
                                              : make_float2(oacc[t].x, oacc[t].y);
                        *(__half2*)&dst[col] = __floats2half2_rn(v.x, v.y);
                    }
                }
            }
        }
    }
}

// ---------------------------------------------------------------------------
extern "C" void kernel_launch(void* const* d_in, const int* in_sizes, int n_in,
                              void* d_out, int out_size)
{
    const float* x      = (const float*)d_in[0];
    const float* qkv_w  = (const float*)d_in[1];
    const float* qkv_b  = (const float*)d_in[2];
    const float* proj_w = (const float*)d_in[3];
    const float* proj_b = (const float*)d_in[4];
    const int*   tmask  = (const int*)d_in[5];
    float* out = (float*)d_out;

    cudaFuncSetAttribute((const void*)gemm_fp16_kernel<0>,
                         cudaFuncAttributeMaxDynamicSharedMemorySize, GSMEM);
    cudaFuncSetAttribute((const void*)gemm_fp16_kernel<1>,
                         cudaFuncAttributeMaxDynamicSharedMemorySize, GSMEM);
    cudaFuncSetAttribute((const void*)attn_fused_kernel,
                         cudaFuncAttributeMaxDynamicSharedMemorySize, DIV5_SMEM_BYTES);

    // 0) fp32 -> fp16 conversion of all GEMM operands (one launch)
    {
        const int n8tot = N8X + N8Q + N8P;
        cvt_all_kernel<<<(n8tot + 255) / 256, 256>>>(x, qkv_w, proj_w);
    }

    // 1) QKV GEMM (static grid, fp16 mma + ldmatrix, 4-stage BK=32)
    gemm_fp16_kernel<0><<<dim3(3 * DIM / 128, (M_TOT + 127) / 128), 256, GSMEM>>>(
        qkv_b, nullptr, M_TOT, 3 * DIM, DIM);

    // 2+3) fused cls (first) + divided spatial attention
    attn_fused_kernel<<<BH + BH * FF, 256, DIV5_SMEM_BYTES>>>(tmask);

    // 4) output projection GEMM (static grid)
    gemm_fp16_kernel<1><<<dim3(DIM / 128, (M_TOT + 127) / 128), 256, GSMEM>>>(
        proj_b, out, M_TOT, DIM, DIM);
}